// round 12
// baseline (speedup 1.0000x reference)
#include <cuda_runtime.h>
#include <cuda_bf16.h>
#include <math.h>
#include <stdint.h>

// ---------------------------------------------------------------------------
// Problem constants
// ---------------------------------------------------------------------------
#define BATCH 2048
#define SEQT  20
#define M_TOK (BATCH*SEQT)   // 40960 tokens
#define NHEAD 4
#define HEADD 64
#define NCLS  1000
#define NLAYER 2

// ---------------------------------------------------------------------------
// Scratch: fp32 intermediates + pre-split bf16 hi/lo operand buffers
// ---------------------------------------------------------------------------
__device__ float g_b1f[(size_t)M_TOK * 1024];
__device__ float g_b2f[(size_t)M_TOK * 256];
__device__ float g_hf [(size_t)M_TOK * 256];

__device__ __nv_bfloat16 g_xh [(size_t)M_TOK * 2048];
__device__ __nv_bfloat16 g_xl [(size_t)M_TOK * 2048];
__device__ __nv_bfloat16 g_b1h[(size_t)M_TOK * 1024];
__device__ __nv_bfloat16 g_b1l[(size_t)M_TOK * 1024];
__device__ __nv_bfloat16 g_b2h[(size_t)M_TOK * 256];
__device__ __nv_bfloat16 g_b2l[(size_t)M_TOK * 256];
__device__ __nv_bfloat16 g_hh [(size_t)M_TOK * 256];
__device__ __nv_bfloat16 g_hl [(size_t)M_TOK * 256];

__device__ __nv_bfloat16 g_w1h[1024*2048],  g_w1l[1024*2048];
__device__ __nv_bfloat16 g_w2h[256*1024],   g_w2l[256*1024];
__device__ __nv_bfloat16 g_wqh[2*768*256],  g_wql[2*768*256];
__device__ __nv_bfloat16 g_woh[2*256*256],  g_wol[2*256*256];
__device__ __nv_bfloat16 g_wf1h[2*1024*256],g_wf1l[2*1024*256];
__device__ __nv_bfloat16 g_wf2h[2*256*1024],g_wf2l[2*256*1024];
__device__ __nv_bfloat16 g_wnh[NCLS*256],   g_wnl[NCLS*256];

// ---------------------------------------------------------------------------
// Helpers
// ---------------------------------------------------------------------------
__device__ __forceinline__ float geluf(float x) {
    return 0.5f * x * (1.0f + erff(x * 0.7071067811865475f));
}
__device__ __forceinline__ float warp_sum(float v) {
    #pragma unroll
    for (int o = 16; o; o >>= 1) v += __shfl_xor_sync(0xffffffffu, v, o);
    return v;
}
__device__ __forceinline__ uint32_t smem_u32(const void* p) {
    uint32_t a;
    asm("{ .reg .u64 t; cvta.to.shared.u64 t, %1; cvt.u32.u64 %0, t; }" : "=r"(a) : "l"(p));
    return a;
}
__device__ __forceinline__ void ldsm4(uint32_t (&r)[4], uint32_t addr) {
    asm volatile("ldmatrix.sync.aligned.m8n8.x4.shared.b16 {%0,%1,%2,%3}, [%4];"
                 : "=r"(r[0]), "=r"(r[1]), "=r"(r[2]), "=r"(r[3]) : "r"(addr));
}
__device__ __forceinline__ void mma16816(float (&d)[4], const uint32_t (&a)[4],
                                         const uint32_t* b) {
    asm volatile("mma.sync.aligned.m16n8k16.row.col.f32.bf16.bf16.f32 "
                 "{%0,%1,%2,%3}, {%4,%5,%6,%7}, {%8,%9}, {%0,%1,%2,%3};"
                 : "+f"(d[0]), "+f"(d[1]), "+f"(d[2]), "+f"(d[3])
                 : "r"(a[0]), "r"(a[1]), "r"(a[2]), "r"(a[3]),
                   "r"(b[0]), "r"(b[1]));
}
__device__ __forceinline__ void cp16(uint32_t dst, const void* src, int sz) {
    asm volatile("cp.async.cg.shared.global [%0], [%1], 16, %2;"
                 :: "r"(dst), "l"(src), "r"(sz) : "memory");
}
#define CP_COMMIT()  asm volatile("cp.async.commit_group;" ::: "memory")
#define CP_WAIT1()   asm volatile("cp.async.wait_group 1;" ::: "memory")
#define CP_WAIT0()   asm volatile("cp.async.wait_group 0;" ::: "memory")

// split one fp32 into hi/lo bf16
__device__ __forceinline__ void split1(float x, __nv_bfloat16& h, __nv_bfloat16& l) {
    h = __float2bfloat16(x);
    l = __float2bfloat16(x - __bfloat162float(h));
}

// ---------------------------------------------------------------------------
// Pure-bf16 3-term GEMM: C = A@W^T where A ~ Ah+Al, W ~ Wh+Wl (bf16 [.,K])
//   EPI 0: fp32 +bias   EPI 1: gelu(+bias) -> split bf16 hi/lo   EPI 2: fp32 *scale
// CTA 128x128, 256 thr (8 warps, 4Mx2N), K-chunk 32, cp.async 2-stage ring,
// hoisted fragments (12 LDSM / 48 MMA per 16-slice). 2 CTAs/SM.
// ---------------------------------------------------------------------------
#define ROWB   80            // 64B data (32 bf16) + 16B pad
#define OFF_AH 0
#define OFF_AL 10240
#define OFF_WH 20480
#define OFF_WL 30720
#define STAGE  40960
#define SMEM_DYN (2*STAGE)   // 81920 B -> 2 CTAs/SM

template<int EPI>
__global__ __launch_bounds__(256, 2)
void gemm_bf3(const __nv_bfloat16* __restrict__ Ah, const __nv_bfloat16* __restrict__ Al,
              const __nv_bfloat16* __restrict__ Wh, const __nv_bfloat16* __restrict__ Wl,
              const float* __restrict__ bias, float* __restrict__ Cf,
              __nv_bfloat16* __restrict__ Ch, __nv_bfloat16* __restrict__ Cl,
              int M, int N, int K, float scale)
{
    extern __shared__ __align__(128) char smem[];
    const uint32_t sb = smem_u32(smem);
    const int tid  = threadIdx.x;
    const int wid  = tid >> 5;
    const int lane = tid & 31;
    const int bm = blockIdx.y * 128;
    const int bn = blockIdx.x * 128;
    const int wm = (wid & 3) * 32;
    const int wn = (wid >> 2) * 64;

    float acc[2][8][4];
    #pragma unroll
    for (int mi = 0; mi < 2; mi++)
        #pragma unroll
        for (int ni = 0; ni < 8; ni++)
            #pragma unroll
            for (int e = 0; e < 4; e++) acc[mi][ni][e] = 0.f;

    // cp.async mapping: 8 x 16B per thread = 4 arrays x 128 rows x 64B
    const int r_ = tid >> 2;        // 0..63
    const int sg = tid & 3;         // 16B segment in row
    auto issue = [&](int c) {
        const uint32_t st = sb + (c & 1) * STAGE;
        const size_t kb = (size_t)c * 64 + sg * 16;   // byte offset within row
        #pragma unroll
        for (int i = 0; i < 8; i++) {
            const int arr = i >> 1;                    // 0:Ah 1:Al 2:Wh 3:Wl
            const int r = r_ + ((i & 1) << 6);         // 0..127
            const uint32_t dst = st + arr * 10240 + r * ROWB + sg * 16;
            const __nv_bfloat16* base;
            int row, sz = 16;
            if (arr < 2) { base = (arr == 0) ? Ah : Al; row = bm + r; }
            else {
                int gn = bn + r;
                if (gn >= N) { gn = N - 1; sz = 0; }
                base = (arr == 2) ? Wh : Wl; row = gn;
            }
            cp16(dst, (const char*)(base + (size_t)row * K * 0 + 0) // placate
                       + (size_t)row * K * 2 + kb, sz);
        }
    };

    // ldsm lane addressing (proven since R5)
    const uint32_t a_row = wm + (lane & 15);
    const uint32_t a_kof = (lane >> 4) << 3;
    const uint32_t b_row = wn + (lane & 7) + (((lane >> 4) & 1) << 3);
    const uint32_t b_kof = ((lane >> 3) & 1) << 3;

    auto mma_chunk = [&](uint32_t st) {
        #pragma unroll
        for (int ks = 0; ks < 2; ks++) {
            const uint32_t k0 = ks << 4;
            uint32_t ah_[2][4], al_[2][4];
            #pragma unroll
            for (int mi = 0; mi < 2; mi++) {
                ldsm4(ah_[mi], st + OFF_AH + (a_row + mi*16) * ROWB + (k0 + a_kof) * 2);
                ldsm4(al_[mi], st + OFF_AL + (a_row + mi*16) * ROWB + (k0 + a_kof) * 2);
            }
            uint32_t bh_[8][2], bl_[8][2];
            #pragma unroll
            for (int nj = 0; nj < 4; nj++) {
                uint32_t r[4];
                ldsm4(r, st + OFF_WH + (b_row + nj*16) * ROWB + (k0 + b_kof) * 2);
                bh_[2*nj][0] = r[0]; bh_[2*nj][1] = r[1];
                bh_[2*nj+1][0] = r[2]; bh_[2*nj+1][1] = r[3];
                ldsm4(r, st + OFF_WL + (b_row + nj*16) * ROWB + (k0 + b_kof) * 2);
                bl_[2*nj][0] = r[0]; bl_[2*nj][1] = r[1];
                bl_[2*nj+1][0] = r[2]; bl_[2*nj+1][1] = r[3];
            }
            #pragma unroll
            for (int mi = 0; mi < 2; mi++)
                #pragma unroll
                for (int ni = 0; ni < 8; ni++) {
                    mma16816(acc[mi][ni], ah_[mi], bh_[ni]);
                    mma16816(acc[mi][ni], al_[mi], bh_[ni]);
                    mma16816(acc[mi][ni], ah_[mi], bl_[ni]);
                }
        }
    };

    const int nch = K >> 5;
    issue(0); CP_COMMIT();
    for (int c = 0; c < nch; c++) {
        if (c + 1 < nch) { issue(c + 1); CP_COMMIT(); CP_WAIT1(); }
        else             { CP_WAIT0(); }
        __syncthreads();                  // all threads' stage-c data visible
        mma_chunk(sb + (c & 1) * STAGE);
        __syncthreads();                  // stage c free for reuse at c+2
    }

    // epilogue
    const int r0 = lane >> 2;
    const int cc0 = (lane & 3) << 1;
    #pragma unroll
    for (int mi = 0; mi < 2; mi++) {
        #pragma unroll
        for (int ni = 0; ni < 8; ni++) {
            int col = bn + wn + ni * 8 + cc0;
            if (col >= N) continue;
            float b0 = 0.f, b1 = 0.f;
            if (EPI != 2 && bias != nullptr) { b0 = bias[col]; b1 = bias[col + 1]; }
            int row = bm + wm + mi * 16 + r0;
            #pragma unroll
            for (int hh = 0; hh < 2; hh++) {
                float t0 = acc[mi][ni][2*hh + 0] + b0;
                float t1 = acc[mi][ni][2*hh + 1] + b1;
                size_t off = (size_t)(row + 8*hh) * N + col;
                if (EPI == 1) {
                    t0 = geluf(t0); t1 = geluf(t1);
                    __nv_bfloat162 hb = __floats2bfloat162_rn(t0, t1);
                    float2 fh = __bfloat1622float2(hb);
                    __nv_bfloat162 lb = __floats2bfloat162_rn(t0 - fh.x, t1 - fh.y);
                    *(__nv_bfloat162*)(Ch + off) = hb;
                    *(__nv_bfloat162*)(Cl + off) = lb;
                } else {
                    if (EPI == 2) { t0 *= scale; t1 *= scale; }
                    float2 o; o.x = t0; o.y = t1;
                    *(float2*)(Cf + off) = o;
                }
            }
        }
    }
}

// ---------------------------------------------------------------------------
// Split fp32 tensor -> hi/lo bf16 (vectorized by 4)
// ---------------------------------------------------------------------------
__global__ void split_f32(const float* __restrict__ src, __nv_bfloat16* __restrict__ dh,
                          __nv_bfloat16* __restrict__ dl, long n4)
{
    long i = (long)blockIdx.x * blockDim.x + threadIdx.x;
    if (i >= n4) return;
    float4 v = ((const float4*)src)[i];
    __nv_bfloat162 h01 = __floats2bfloat162_rn(v.x, v.y);
    __nv_bfloat162 h23 = __floats2bfloat162_rn(v.z, v.w);
    float2 f01 = __bfloat1622float2(h01);
    float2 f23 = __bfloat1622float2(h23);
    __nv_bfloat162 l01 = __floats2bfloat162_rn(v.x - f01.x, v.y - f01.y);
    __nv_bfloat162 l23 = __floats2bfloat162_rn(v.z - f23.x, v.w - f23.y);
    uint2 hu; hu.x = *(uint32_t*)&h01; hu.y = *(uint32_t*)&h23;
    uint2 lu; lu.x = *(uint32_t*)&l01; lu.y = *(uint32_t*)&l23;
    ((uint2*)dh)[i] = hu;
    ((uint2*)dl)[i] = lu;
}

// ---------------------------------------------------------------------------
// Elementwise kernels (write hi/lo bf16 for downstream GEMMs)
// ---------------------------------------------------------------------------
__global__ void ln_gelu_1024(const float* __restrict__ buf,
                             __nv_bfloat16* __restrict__ dh, __nv_bfloat16* __restrict__ dl,
                             const float* __restrict__ w, const float* __restrict__ b)
{
    int row = blockIdx.x;
    const float4* p = (const float4*)(buf + (size_t)row * 1024);
    int tid = threadIdx.x;
    float4 x = p[tid];
    float s  = x.x + x.y + x.z + x.w;
    float ss = x.x*x.x + x.y*x.y + x.z*x.z + x.w*x.w;
    __shared__ float sh[2][8];
    float ws_ = warp_sum(s), wss = warp_sum(ss);
    if ((tid & 31) == 0) { sh[0][tid >> 5] = ws_; sh[1][tid >> 5] = wss; }
    __syncthreads();
    float tot = 0.f, tot2 = 0.f;
    #pragma unroll
    for (int i = 0; i < 8; i++) { tot += sh[0][i]; tot2 += sh[1][i]; }
    float mean = tot * (1.f / 1024.f);
    float var  = tot2 * (1.f / 1024.f) - mean * mean;
    float rstd = rsqrtf(var + 1e-6f);
    float4 wv = ((const float4*)w)[tid];
    float4 bv = ((const float4*)b)[tid];
    float y0 = geluf((x.x - mean) * rstd * wv.x + bv.x);
    float y1 = geluf((x.y - mean) * rstd * wv.y + bv.y);
    float y2 = geluf((x.z - mean) * rstd * wv.z + bv.z);
    float y3 = geluf((x.w - mean) * rstd * wv.w + bv.w);
    __nv_bfloat162 h01 = __floats2bfloat162_rn(y0, y1);
    __nv_bfloat162 h23 = __floats2bfloat162_rn(y2, y3);
    float2 f01 = __bfloat1622float2(h01);
    float2 f23 = __bfloat1622float2(h23);
    __nv_bfloat162 l01 = __floats2bfloat162_rn(y0 - f01.x, y1 - f01.y);
    __nv_bfloat162 l23 = __floats2bfloat162_rn(y2 - f23.x, y3 - f23.y);
    uint2 hu; hu.x = *(uint32_t*)&h01; hu.y = *(uint32_t*)&h23;
    uint2 lu; lu.x = *(uint32_t*)&l01; lu.y = *(uint32_t*)&l23;
    ((uint2*)(dh + (size_t)row * 1024))[tid] = hu;
    ((uint2*)(dl + (size_t)row * 1024))[tid] = lu;
}

__global__ void ln_pe_256(const float* __restrict__ src, float* __restrict__ hf,
                          __nv_bfloat16* __restrict__ hh, __nv_bfloat16* __restrict__ hl,
                          const float* __restrict__ w, const float* __restrict__ b)
{
    int row  = blockIdx.x * 8 + (threadIdx.x >> 5);
    int lane = threadIdx.x & 31;
    const float* x = src + (size_t)row * 256;
    float v[8], s = 0.f, ss = 0.f;
    #pragma unroll
    for (int i = 0; i < 8; i++) { v[i] = x[lane + 32*i]; s += v[i]; ss += v[i]*v[i]; }
    s = warp_sum(s); ss = warp_sum(ss);
    float mean = s * (1.f/256.f);
    float var  = ss * (1.f/256.f) - mean*mean;
    float rstd = rsqrtf(var + 1e-6f);
    int t = row % SEQT;
    size_t base = (size_t)row * 256;
    #pragma unroll
    for (int i = 0; i < 8; i++) {
        int c = lane + 32*i;
        int j = c & ~1;
        float ang = (float)t * expf((float)j * (-9.210340371976184f / 256.f));
        float pe  = (c & 1) ? cosf(ang) : sinf(ang);
        float y = (v[i] - mean) * rstd * w[c] + b[c] + pe;
        hf[base + c] = y;
        __nv_bfloat16 yh, yl; split1(y, yh, yl);
        hh[base + c] = yh; hl[base + c] = yl;
    }
}

__global__ void resln_256(float* __restrict__ hf, const float* __restrict__ r,
                          __nv_bfloat16* __restrict__ hh, __nv_bfloat16* __restrict__ hl,
                          const float* __restrict__ w, const float* __restrict__ b)
{
    int row  = blockIdx.x * 8 + (threadIdx.x >> 5);
    int lane = threadIdx.x & 31;
    float* hp = hf + (size_t)row * 256;
    const float* rp = r + (size_t)row * 256;
    float v[8], s = 0.f, ss = 0.f;
    #pragma unroll
    for (int i = 0; i < 8; i++) {
        int c = lane + 32*i;
        v[i] = hp[c] + rp[c];
        s += v[i]; ss += v[i]*v[i];
    }
    s = warp_sum(s); ss = warp_sum(ss);
    float mean = s * (1.f/256.f);
    float var  = ss * (1.f/256.f) - mean*mean;
    float rstd = rsqrtf(var + 1e-6f);
    size_t base = (size_t)row * 256;
    #pragma unroll
    for (int i = 0; i < 8; i++) {
        int c = lane + 32*i;
        float y = (v[i] - mean) * rstd * w[c] + b[c];
        hp[c] = y;
        __nv_bfloat16 yh, yl; split1(y, yh, yl);
        hh[base + c] = yh; hl[base + c] = yl;
    }
}

// l2-normalize rows of 256, output hi/lo bf16
__global__ void norm_rows_256(const float* __restrict__ src,
                              __nv_bfloat16* __restrict__ oh, __nv_bfloat16* __restrict__ ol,
                              int nrows)
{
    int row  = blockIdx.x * 8 + (threadIdx.x >> 5);
    int lane = threadIdx.x & 31;
    if (row >= nrows) return;
    const float* x = src + (size_t)row * 256;
    float v[8], ss = 0.f;
    #pragma unroll
    for (int i = 0; i < 8; i++) { v[i] = x[lane + 32*i]; ss += v[i]*v[i]; }
    ss = warp_sum(ss);
    float inv = 1.f / fmaxf(sqrtf(ss), 1e-12f);
    size_t base = (size_t)row * 256;
    #pragma unroll
    for (int i = 0; i < 8; i++) {
        int c = lane + 32*i;
        float y = v[i] * inv;
        __nv_bfloat16 yh, yl; split1(y, yh, yl);
        oh[base + c] = yh; ol[base + c] = yl;
    }
}

__global__ void attn_kernel(const float* __restrict__ qkv,
                            __nv_bfloat16* __restrict__ oh, __nv_bfloat16* __restrict__ ol)
{
    int bh = blockIdx.x;
    int bidx = bh / NHEAD;
    int hh   = bh % NHEAD;
    __shared__ float q[SEQT][HEADD];
    __shared__ float k[SEQT][HEADD];
    __shared__ float v[SEQT][HEADD];
    __shared__ float p[SEQT][SEQT];
    int tid = threadIdx.x;

    for (int idx = tid; idx < SEQT * HEADD; idx += 256) {
        int t = idx / HEADD, d = idx % HEADD;
        size_t off = (size_t)(bidx * SEQT + t) * 768 + hh * HEADD + d;
        q[t][d] = qkv[off];
        k[t][d] = qkv[off + 256];
        v[t][d] = qkv[off + 512];
    }
    __syncthreads();

    for (int idx = tid; idx < SEQT * SEQT; idx += 256) {
        int t = idx / SEQT, s = idx % SEQT;
        if (s <= t) {
            float acc = 0.f;
            #pragma unroll
            for (int d = 0; d < HEADD; d++) acc += q[t][d] * k[s][d];
            p[t][s] = acc * 0.125f;
        } else p[t][s] = 0.f;
    }
    __syncthreads();

    if (tid < SEQT) {
        int t = tid;
        float mx = -1e30f;
        for (int s = 0; s <= t; s++) mx = fmaxf(mx, p[t][s]);
        float sum = 0.f;
        for (int s = 0; s <= t; s++) { float e = expf(p[t][s] - mx); p[t][s] = e; sum += e; }
        float inv = 1.f / sum;
        for (int s = 0; s <= t; s++) p[t][s] *= inv;
        for (int s = t + 1; s < SEQT; s++) p[t][s] = 0.f;
    }
    __syncthreads();

    for (int idx = tid; idx < SEQT * HEADD; idx += 256) {
        int t = idx / HEADD, d = idx % HEADD;
        float acc = 0.f;
        for (int s = 0; s <= t; s++) acc += p[t][s] * v[s][d];
        size_t off = (size_t)(bidx * SEQT + t) * 256 + hh * HEADD + d;
        __nv_bfloat16 yh, yl; split1(acc, yh, yl);
        oh[off] = yh; ol[off] = yl;
    }
}

// ---------------------------------------------------------------------------
// Launch
// ---------------------------------------------------------------------------
extern "C" void kernel_launch(void* const* d_in, const int* in_sizes, int n_in,
                              void* d_out, int out_size)
{
    const float* x         = (const float*)d_in[0];
    const float* p1_w      = (const float*)d_in[1];
    const float* p1_b      = (const float*)d_in[2];
    const float* pln1_w    = (const float*)d_in[3];
    const float* pln1_b    = (const float*)d_in[4];
    const float* p2_w      = (const float*)d_in[5];
    const float* pln2_w    = (const float*)d_in[6];
    const float* pln2_b    = (const float*)d_in[7];
    const float* in_proj_w = (const float*)d_in[8];
    const float* in_proj_b = (const float*)d_in[9];
    const float* out_proj_w= (const float*)d_in[10];
    const float* out_proj_b= (const float*)d_in[11];
    const float* ln1_w     = (const float*)d_in[12];
    const float* ln1_b     = (const float*)d_in[13];
    const float* lin1_w    = (const float*)d_in[14];
    const float* lin1_b    = (const float*)d_in[15];
    const float* lin2_w    = (const float*)d_in[16];
    const float* lin2_b    = (const float*)d_in[17];
    const float* ln2_w     = (const float*)d_in[18];
    const float* ln2_b     = (const float*)d_in[19];
    const float* head_w    = (const float*)d_in[20];
    float* out = (float*)d_out;

    float *b1f, *b2f, *hf;
    __nv_bfloat16 *xh,*xl,*b1h,*b1l,*b2h,*b2l,*hh,*hl;
    __nv_bfloat16 *w1h,*w1l,*w2h,*w2l,*wqh,*wql,*woh,*wol,*wf1h,*wf1l,*wf2h,*wf2l,*wnh,*wnl;
    cudaGetSymbolAddress((void**)&b1f, g_b1f);
    cudaGetSymbolAddress((void**)&b2f, g_b2f);
    cudaGetSymbolAddress((void**)&hf,  g_hf);
    cudaGetSymbolAddress((void**)&xh,  g_xh);  cudaGetSymbolAddress((void**)&xl,  g_xl);
    cudaGetSymbolAddress((void**)&b1h, g_b1h); cudaGetSymbolAddress((void**)&b1l, g_b1l);
    cudaGetSymbolAddress((void**)&b2h, g_b2h); cudaGetSymbolAddress((void**)&b2l, g_b2l);
    cudaGetSymbolAddress((void**)&hh,  g_hh);  cudaGetSymbolAddress((void**)&hl,  g_hl);
    cudaGetSymbolAddress((void**)&w1h, g_w1h); cudaGetSymbolAddress((void**)&w1l, g_w1l);
    cudaGetSymbolAddress((void**)&w2h, g_w2h); cudaGetSymbolAddress((void**)&w2l, g_w2l);
    cudaGetSymbolAddress((void**)&wqh, g_wqh); cudaGetSymbolAddress((void**)&wql, g_wql);
    cudaGetSymbolAddress((void**)&woh, g_woh); cudaGetSymbolAddress((void**)&wol, g_wol);
    cudaGetSymbolAddress((void**)&wf1h, g_wf1h); cudaGetSymbolAddress((void**)&wf1l, g_wf1l);
    cudaGetSymbolAddress((void**)&wf2h, g_wf2h); cudaGetSymbolAddress((void**)&wf2l, g_wf2l);
    cudaGetSymbolAddress((void**)&wnh, g_wnh); cudaGetSymbolAddress((void**)&wnl, g_wnl);

    cudaFuncSetAttribute(gemm_bf3<0>, cudaFuncAttributeMaxDynamicSharedMemorySize, SMEM_DYN);
    cudaFuncSetAttribute(gemm_bf3<1>, cudaFuncAttributeMaxDynamicSharedMemorySize, SMEM_DYN);
    cudaFuncSetAttribute(gemm_bf3<2>, cudaFuncAttributeMaxDynamicSharedMemorySize, SMEM_DYN);

    const int M = M_TOK;
    const dim3 blk(256);
    const int MB = M / 128;  // 320
    #define GRID(N_) dim3(((N_) + 127) / 128, MB)
    #define SPLIT(src, dh, dl, n) do { long n4 = (long)(n) / 4; \
        split_f32<<<(unsigned)((n4 + 255) / 256), 256>>>(src, dh, dl, n4); } while (0)

    // one-time splits (input + all weights)
    SPLIT(x, xh, xl, (long)M * 2048);
    SPLIT(p1_w, w1h, w1l, 1024L * 2048);
    SPLIT(p2_w, w2h, w2l, 256L * 1024);
    SPLIT(in_proj_w, wqh, wql, 2L * 768 * 256);
    SPLIT(out_proj_w, woh, wol, 2L * 256 * 256);
    SPLIT(lin1_w, wf1h, wf1l, 2L * 1024 * 256);
    SPLIT(lin2_w, wf2h, wf2l, 2L * 256 * 1024);

    // projector
    gemm_bf3<0><<<GRID(1024), blk, SMEM_DYN>>>(xh, xl, w1h, w1l, p1_b, b1f,
                                               nullptr, nullptr, M, 1024, 2048, 1.f);
    ln_gelu_1024<<<M, blk>>>(b1f, b1h, b1l, pln1_w, pln1_b);
    gemm_bf3<0><<<GRID(256), blk, SMEM_DYN>>>(b1h, b1l, w2h, w2l, nullptr, b2f,
                                              nullptr, nullptr, M, 256, 1024, 1.f);
    ln_pe_256<<<M / 8, blk>>>(b2f, hf, hh, hl, pln2_w, pln2_b);

    // transformer layers
    for (int i = 0; i < NLAYER; i++) {
        const __nv_bfloat16* iqh = wqh + (size_t)i * 768 * 256;
        const __nv_bfloat16* iql = wql + (size_t)i * 768 * 256;
        const __nv_bfloat16* ioh = woh + (size_t)i * 256 * 256;
        const __nv_bfloat16* iol = wol + (size_t)i * 256 * 256;
        const __nv_bfloat16* if1h = wf1h + (size_t)i * 1024 * 256;
        const __nv_bfloat16* if1l = wf1l + (size_t)i * 1024 * 256;
        const __nv_bfloat16* if2h = wf2h + (size_t)i * 256 * 1024;
        const __nv_bfloat16* if2l = wf2l + (size_t)i * 256 * 1024;
        const float* ipb = in_proj_b + (size_t)i * 768;
        const float* opb = out_proj_b + (size_t)i * 256;
        const float* l1b = lin1_b + (size_t)i * 1024;
        const float* l2b = lin2_b + (size_t)i * 256;

        gemm_bf3<0><<<GRID(768), blk, SMEM_DYN>>>(hh, hl, iqh, iql, ipb, b1f,
                                                  nullptr, nullptr, M, 768, 256, 1.f);
        attn_kernel<<<BATCH * NHEAD, blk>>>(b1f, b2h, b2l);
        gemm_bf3<0><<<GRID(256), blk, SMEM_DYN>>>(b2h, b2l, ioh, iol, opb, b2f,
                                                  nullptr, nullptr, M, 256, 256, 1.f);
        resln_256<<<M / 8, blk>>>(hf, b2f, hh, hl,
                                  ln1_w + (size_t)i * 256, ln1_b + (size_t)i * 256);
        gemm_bf3<1><<<GRID(1024), blk, SMEM_DYN>>>(hh, hl, if1h, if1l, l1b, nullptr,
                                                   b1h, b1l, M, 1024, 256, 1.f);
        gemm_bf3<0><<<GRID(256), blk, SMEM_DYN>>>(b1h, b1l, if2h, if2l, l2b, b2f,
                                                  nullptr, nullptr, M, 256, 1024, 1.f);
        resln_256<<<M / 8, blk>>>(hf, b2f, hh, hl,
                                  ln2_w + (size_t)i * 256, ln2_b + (size_t)i * 256);
    }

    // cosine head
    norm_rows_256<<<M / 8, blk>>>(hf, b2h, b2l, M);
    norm_rows_256<<<(NCLS + 7) / 8, blk>>>(head_w, wnh, wnl, NCLS);
    gemm_bf3<2><<<GRID(NCLS), blk, SMEM_DYN>>>(b2h, b2l, wnh, wnl, nullptr, out,
                                               nullptr, nullptr, M, NCLS, 256, 10.f);
}

// round 13
// speedup vs baseline: 1.2387x; 1.2387x over previous
#include <cuda_runtime.h>
#include <cuda_fp16.h>
#include <math.h>
#include <stdint.h>

// ---------------------------------------------------------------------------
// Problem constants
// ---------------------------------------------------------------------------
#define BATCH 2048
#define SEQT  20
#define M_TOK (BATCH*SEQT)   // 40960 tokens
#define NHEAD 4
#define HEADD 64
#define NCLS  1000
#define NLAYER 2

// ---------------------------------------------------------------------------
// Scratch: fp32 intermediates + fp16 operand buffers (A-side split hi/lo,
// W-side single fp16)
// ---------------------------------------------------------------------------
__device__ float g_b1f[(size_t)M_TOK * 1024];
__device__ float g_b2f[(size_t)M_TOK * 256];
__device__ float g_hf [(size_t)M_TOK * 256];

__device__ __half g_xh [(size_t)M_TOK * 2048];
__device__ __half g_xl [(size_t)M_TOK * 2048];
__device__ __half g_b1h[(size_t)M_TOK * 1024];
__device__ __half g_b1l[(size_t)M_TOK * 1024];
__device__ __half g_b2h[(size_t)M_TOK * 256];
__device__ __half g_b2l[(size_t)M_TOK * 256];
__device__ __half g_hh [(size_t)M_TOK * 256];
__device__ __half g_hl [(size_t)M_TOK * 256];

__device__ __half g_w1 [1024*2048];
__device__ __half g_w2 [256*1024];
__device__ __half g_wq [2*768*256];
__device__ __half g_wo [2*256*256];
__device__ __half g_wf1[2*1024*256];
__device__ __half g_wf2[2*256*1024];
__device__ __half g_wn [NCLS*256];

// ---------------------------------------------------------------------------
// Helpers
// ---------------------------------------------------------------------------
__device__ __forceinline__ float geluf(float x) {
    return 0.5f * x * (1.0f + erff(x * 0.7071067811865475f));
}
__device__ __forceinline__ float warp_sum(float v) {
    #pragma unroll
    for (int o = 16; o; o >>= 1) v += __shfl_xor_sync(0xffffffffu, v, o);
    return v;
}
__device__ __forceinline__ uint32_t smem_u32(const void* p) {
    uint32_t a;
    asm("{ .reg .u64 t; cvta.to.shared.u64 t, %1; cvt.u32.u64 %0, t; }" : "=r"(a) : "l"(p));
    return a;
}
__device__ __forceinline__ void ldsm4(uint32_t (&r)[4], uint32_t addr) {
    asm volatile("ldmatrix.sync.aligned.m8n8.x4.shared.b16 {%0,%1,%2,%3}, [%4];"
                 : "=r"(r[0]), "=r"(r[1]), "=r"(r[2]), "=r"(r[3]) : "r"(addr));
}
__device__ __forceinline__ void mma16816h(float (&d)[4], const uint32_t (&a)[4],
                                          const uint32_t* b) {
    asm volatile("mma.sync.aligned.m16n8k16.row.col.f32.f16.f16.f32 "
                 "{%0,%1,%2,%3}, {%4,%5,%6,%7}, {%8,%9}, {%0,%1,%2,%3};"
                 : "+f"(d[0]), "+f"(d[1]), "+f"(d[2]), "+f"(d[3])
                 : "r"(a[0]), "r"(a[1]), "r"(a[2]), "r"(a[3]),
                   "r"(b[0]), "r"(b[1]));
}
__device__ __forceinline__ void cp16(uint32_t dst, const void* src, int sz) {
    asm volatile("cp.async.cg.shared.global [%0], [%1], 16, %2;"
                 :: "r"(dst), "l"(src), "r"(sz) : "memory");
}
#define CP_COMMIT()  asm volatile("cp.async.commit_group;" ::: "memory")
#define CP_WAIT1()   asm volatile("cp.async.wait_group 1;" ::: "memory")
#define CP_WAIT0()   asm volatile("cp.async.wait_group 0;" ::: "memory")

__device__ __forceinline__ void split1h(float x, __half& h, __half& l) {
    h = __float2half_rn(x);
    l = __float2half_rn(x - __half2float(h));
}

// ---------------------------------------------------------------------------
// fp16 2-term GEMM: C = A@W^T, A ~ Ah+Al (fp16), W ~ fp16 single
//   EPI 0: fp32 +bias   EPI 1: gelu(+bias) -> fp16 hi/lo   EPI 2: fp32 *scale
// CTA 128x128, 256 thr (8 warps, 4Mx2N), K-chunk 32, cp.async 2-stage ring.
// 2 CTAs/SM. M%128==0, K%32==0, N%2==0.
// ---------------------------------------------------------------------------
#define ROWB   80            // 64B data (32 fp16) + 16B pad
#define OFF_AH 0
#define OFF_AL 10240
#define OFF_WH 20480
#define STAGE  30720
#define SMEM_DYN (2*STAGE)   // 61440 B -> 2 CTAs/SM = 122880 B

template<int EPI>
__global__ __launch_bounds__(256, 2)
void gemm_fp2(const __half* __restrict__ Ah, const __half* __restrict__ Al,
              const __half* __restrict__ Wh,
              const float* __restrict__ bias, float* __restrict__ Cf,
              __half* __restrict__ Ch, __half* __restrict__ Cl,
              int M, int N, int K, float scale)
{
    extern __shared__ __align__(128) char smem[];
    const uint32_t sb = smem_u32(smem);
    const int tid  = threadIdx.x;
    const int wid  = tid >> 5;
    const int lane = tid & 31;
    const int bm = blockIdx.y * 128;
    const int bn = blockIdx.x * 128;
    const int wm = (wid & 3) * 32;
    const int wn = (wid >> 2) * 64;

    float acc[2][8][4];
    #pragma unroll
    for (int mi = 0; mi < 2; mi++)
        #pragma unroll
        for (int ni = 0; ni < 8; ni++)
            #pragma unroll
            for (int e = 0; e < 4; e++) acc[mi][ni][e] = 0.f;

    // cp.async: 3 arrays x 128 rows x 64B per chunk = 1536 x 16B = 6/thread
    const int r_ = tid >> 2;        // 0..63
    const int sg = tid & 3;         // 16B segment within 64B row-chunk
    auto issue = [&](int c) {
        const uint32_t st = sb + (c & 1) * STAGE;
        const size_t kb = (size_t)c * 64 + sg * 16;   // byte offset in row
        #pragma unroll
        for (int i = 0; i < 6; i++) {
            const int arr = i >> 1;                    // 0:Ah 1:Al 2:Wh
            const int r = r_ + ((i & 1) << 6);         // 0..127
            const uint32_t dst = st + arr * 10240 + r * ROWB + sg * 16;
            const __half* base;
            int row, sz = 16;
            if (arr < 2) { base = (arr == 0) ? Ah : Al; row = bm + r; }
            else {
                int gn = bn + r;
                if (gn >= N) { gn = N - 1; sz = 0; }
                base = Wh; row = gn;
            }
            cp16(dst, (const char*)base + (size_t)row * K * 2 + kb, sz);
        }
    };

    // ldsm lane addressing (proven since R5)
    const uint32_t a_row = wm + (lane & 15);
    const uint32_t a_kof = (lane >> 4) << 3;
    const uint32_t b_row = wn + (lane & 7) + (((lane >> 4) & 1) << 3);
    const uint32_t b_kof = ((lane >> 3) & 1) << 3;

    auto mma_chunk = [&](uint32_t st) {
        #pragma unroll
        for (int ks = 0; ks < 2; ks++) {
            const uint32_t k0 = ks << 4;
            uint32_t ah_[2][4], al_[2][4];
            #pragma unroll
            for (int mi = 0; mi < 2; mi++) {
                ldsm4(ah_[mi], st + OFF_AH + (a_row + mi*16) * ROWB + (k0 + a_kof) * 2);
                ldsm4(al_[mi], st + OFF_AL + (a_row + mi*16) * ROWB + (k0 + a_kof) * 2);
            }
            uint32_t bh_[8][2];
            #pragma unroll
            for (int nj = 0; nj < 4; nj++) {
                uint32_t r[4];
                ldsm4(r, st + OFF_WH + (b_row + nj*16) * ROWB + (k0 + b_kof) * 2);
                bh_[2*nj][0] = r[0]; bh_[2*nj][1] = r[1];
                bh_[2*nj+1][0] = r[2]; bh_[2*nj+1][1] = r[3];
            }
            #pragma unroll
            for (int mi = 0; mi < 2; mi++)
                #pragma unroll
                for (int ni = 0; ni < 8; ni++) {
                    mma16816h(acc[mi][ni], ah_[mi], bh_[ni]);
                    mma16816h(acc[mi][ni], al_[mi], bh_[ni]);
                }
        }
    };

    const int nch = K >> 5;
    issue(0); CP_COMMIT();
    for (int c = 0; c < nch; c++) {
        if (c + 1 < nch) { issue(c + 1); CP_COMMIT(); CP_WAIT1(); }
        else             { CP_WAIT0(); }
        __syncthreads();
        mma_chunk(sb + (c & 1) * STAGE);
        __syncthreads();
    }

    // epilogue
    const int r0 = lane >> 2;
    const int cc0 = (lane & 3) << 1;
    #pragma unroll
    for (int mi = 0; mi < 2; mi++) {
        #pragma unroll
        for (int ni = 0; ni < 8; ni++) {
            int col = bn + wn + ni * 8 + cc0;
            if (col >= N) continue;
            float b0 = 0.f, b1 = 0.f;
            if (EPI != 2 && bias != nullptr) { b0 = bias[col]; b1 = bias[col + 1]; }
            int row = bm + wm + mi * 16 + r0;
            #pragma unroll
            for (int hh = 0; hh < 2; hh++) {
                float t0 = acc[mi][ni][2*hh + 0] + b0;
                float t1 = acc[mi][ni][2*hh + 1] + b1;
                size_t off = (size_t)(row + 8*hh) * N + col;
                if (EPI == 1) {
                    t0 = geluf(t0); t1 = geluf(t1);
                    __half h0, l0, h1, l1;
                    split1h(t0, h0, l0); split1h(t1, h1, l1);
                    *(__half2*)(Ch + off) = __halves2half2(h0, h1);
                    *(__half2*)(Cl + off) = __halves2half2(l0, l1);
                } else {
                    if (EPI == 2) { t0 *= scale; t1 *= scale; }
                    float2 o; o.x = t0; o.y = t1;
                    *(float2*)(Cf + off) = o;
                }
            }
        }
    }
}

// ---------------------------------------------------------------------------
// Split fp32 -> fp16 hi/lo (vectorized by 4)
// ---------------------------------------------------------------------------
__global__ void split_f32h(const float* __restrict__ src, __half* __restrict__ dh,
                           __half* __restrict__ dl, long n4)
{
    long i = (long)blockIdx.x * blockDim.x + threadIdx.x;
    if (i >= n4) return;
    float4 v = ((const float4*)src)[i];
    __half h0, l0, h1, l1, h2, l2, h3, l3;
    split1h(v.x, h0, l0); split1h(v.y, h1, l1);
    split1h(v.z, h2, l2); split1h(v.w, h3, l3);
    __half2 H01 = __halves2half2(h0, h1), H23 = __halves2half2(h2, h3);
    __half2 L01 = __halves2half2(l0, l1), L23 = __halves2half2(l2, l3);
    uint2 hu; hu.x = *(uint32_t*)&H01; hu.y = *(uint32_t*)&H23;
    uint2 lu; lu.x = *(uint32_t*)&L01; lu.y = *(uint32_t*)&L23;
    ((uint2*)dh)[i] = hu;
    ((uint2*)dl)[i] = lu;
}

// Convert fp32 -> single fp16 (vectorized by 4)
__global__ void conv_f16(const float* __restrict__ src, __half* __restrict__ dst, long n4)
{
    long i = (long)blockIdx.x * blockDim.x + threadIdx.x;
    if (i >= n4) return;
    float4 v = ((const float4*)src)[i];
    __half2 a = __floats2half2_rn(v.x, v.y);
    __half2 b = __floats2half2_rn(v.z, v.w);
    uint2 u; u.x = *(uint32_t*)&a; u.y = *(uint32_t*)&b;
    ((uint2*)dst)[i] = u;
}

// ---------------------------------------------------------------------------
// Elementwise kernels (A-side producers write fp16 hi/lo)
// ---------------------------------------------------------------------------
__global__ void ln_gelu_1024(const float* __restrict__ buf,
                             __half* __restrict__ dh, __half* __restrict__ dl,
                             const float* __restrict__ w, const float* __restrict__ b)
{
    int row = blockIdx.x;
    const float4* p = (const float4*)(buf + (size_t)row * 1024);
    int tid = threadIdx.x;
    float4 x = p[tid];
    float s  = x.x + x.y + x.z + x.w;
    float ss = x.x*x.x + x.y*x.y + x.z*x.z + x.w*x.w;
    __shared__ float sh[2][8];
    float ws_ = warp_sum(s), wss = warp_sum(ss);
    if ((tid & 31) == 0) { sh[0][tid >> 5] = ws_; sh[1][tid >> 5] = wss; }
    __syncthreads();
    float tot = 0.f, tot2 = 0.f;
    #pragma unroll
    for (int i = 0; i < 8; i++) { tot += sh[0][i]; tot2 += sh[1][i]; }
    float mean = tot * (1.f / 1024.f);
    float var  = tot2 * (1.f / 1024.f) - mean * mean;
    float rstd = rsqrtf(var + 1e-6f);
    float4 wv = ((const float4*)w)[tid];
    float4 bv = ((const float4*)b)[tid];
    float y0 = geluf((x.x - mean) * rstd * wv.x + bv.x);
    float y1 = geluf((x.y - mean) * rstd * wv.y + bv.y);
    float y2 = geluf((x.z - mean) * rstd * wv.z + bv.z);
    float y3 = geluf((x.w - mean) * rstd * wv.w + bv.w);
    __half h0,l0,h1,l1,h2,l2,h3,l3;
    split1h(y0,h0,l0); split1h(y1,h1,l1); split1h(y2,h2,l2); split1h(y3,h3,l3);
    __half2 H01 = __halves2half2(h0,h1), H23 = __halves2half2(h2,h3);
    __half2 L01 = __halves2half2(l0,l1), L23 = __halves2half2(l2,l3);
    uint2 hu; hu.x = *(uint32_t*)&H01; hu.y = *(uint32_t*)&H23;
    uint2 lu; lu.x = *(uint32_t*)&L01; lu.y = *(uint32_t*)&L23;
    ((uint2*)(dh + (size_t)row * 1024))[tid] = hu;
    ((uint2*)(dl + (size_t)row * 1024))[tid] = lu;
}

__global__ void ln_pe_256(const float* __restrict__ src, float* __restrict__ hf,
                          __half* __restrict__ hh, __half* __restrict__ hl,
                          const float* __restrict__ w, const float* __restrict__ b)
{
    int row  = blockIdx.x * 8 + (threadIdx.x >> 5);
    int lane = threadIdx.x & 31;
    const float* x = src + (size_t)row * 256;
    float v[8], s = 0.f, ss = 0.f;
    #pragma unroll
    for (int i = 0; i < 8; i++) { v[i] = x[lane + 32*i]; s += v[i]; ss += v[i]*v[i]; }
    s = warp_sum(s); ss = warp_sum(ss);
    float mean = s * (1.f/256.f);
    float var  = ss * (1.f/256.f) - mean*mean;
    float rstd = rsqrtf(var + 1e-6f);
    int t = row % SEQT;
    size_t base = (size_t)row * 256;
    #pragma unroll
    for (int i = 0; i < 8; i++) {
        int c = lane + 32*i;
        int j = c & ~1;
        float ang = (float)t * expf((float)j * (-9.210340371976184f / 256.f));
        float pe  = (c & 1) ? cosf(ang) : sinf(ang);
        float y = (v[i] - mean) * rstd * w[c] + b[c] + pe;
        hf[base + c] = y;
        __half yh, yl; split1h(y, yh, yl);
        hh[base + c] = yh; hl[base + c] = yl;
    }
}

__global__ void resln_256(float* __restrict__ hf, const float* __restrict__ r,
                          __half* __restrict__ hh, __half* __restrict__ hl,
                          const float* __restrict__ w, const float* __restrict__ b)
{
    int row  = blockIdx.x * 8 + (threadIdx.x >> 5);
    int lane = threadIdx.x & 31;
    float* hp = hf + (size_t)row * 256;
    const float* rp = r + (size_t)row * 256;
    float v[8], s = 0.f, ss = 0.f;
    #pragma unroll
    for (int i = 0; i < 8; i++) {
        int c = lane + 32*i;
        v[i] = hp[c] + rp[c];
        s += v[i]; ss += v[i]*v[i];
    }
    s = warp_sum(s); ss = warp_sum(ss);
    float mean = s * (1.f/256.f);
    float var  = ss * (1.f/256.f) - mean*mean;
    float rstd = rsqrtf(var + 1e-6f);
    size_t base = (size_t)row * 256;
    #pragma unroll
    for (int i = 0; i < 8; i++) {
        int c = lane + 32*i;
        float y = (v[i] - mean) * rstd * w[c] + b[c];
        hp[c] = y;
        __half yh, yl; split1h(y, yh, yl);
        hh[base + c] = yh; hl[base + c] = yl;
    }
}

// l2-normalize rows of 256 -> fp16 hi/lo
__global__ void norm_rows_256(const float* __restrict__ src,
                              __half* __restrict__ oh, __half* __restrict__ ol,
                              int nrows)
{
    int row  = blockIdx.x * 8 + (threadIdx.x >> 5);
    int lane = threadIdx.x & 31;
    if (row >= nrows) return;
    const float* x = src + (size_t)row * 256;
    float v[8], ss = 0.f;
    #pragma unroll
    for (int i = 0; i < 8; i++) { v[i] = x[lane + 32*i]; ss += v[i]*v[i]; }
    ss = warp_sum(ss);
    float inv = 1.f / fmaxf(sqrtf(ss), 1e-12f);
    size_t base = (size_t)row * 256;
    #pragma unroll
    for (int i = 0; i < 8; i++) {
        int c = lane + 32*i;
        float y = v[i] * inv;
        __half yh, yl; split1h(y, yh, yl);
        oh[base + c] = yh;
        if (ol) ol[base + c] = yl;
    }
}

__global__ void attn_kernel(const float* __restrict__ qkv,
                            __half* __restrict__ oh, __half* __restrict__ ol)
{
    int bh = blockIdx.x;
    int bidx = bh / NHEAD;
    int hh   = bh % NHEAD;
    __shared__ float q[SEQT][HEADD];
    __shared__ float k[SEQT][HEADD];
    __shared__ float v[SEQT][HEADD];
    __shared__ float p[SEQT][SEQT];
    int tid = threadIdx.x;

    for (int idx = tid; idx < SEQT * HEADD; idx += 256) {
        int t = idx / HEADD, d = idx % HEADD;
        size_t off = (size_t)(bidx * SEQT + t) * 768 + hh * HEADD + d;
        q[t][d] = qkv[off];
        k[t][d] = qkv[off + 256];
        v[t][d] = qkv[off + 512];
    }
    __syncthreads();

    for (int idx = tid; idx < SEQT * SEQT; idx += 256) {
        int t = idx / SEQT, s = idx % SEQT;
        if (s <= t) {
            float acc = 0.f;
            #pragma unroll
            for (int d = 0; d < HEADD; d++) acc += q[t][d] * k[s][d];
            p[t][s] = acc * 0.125f;
        } else p[t][s] = 0.f;
    }
    __syncthreads();

    if (tid < SEQT) {
        int t = tid;
        float mx = -1e30f;
        for (int s = 0; s <= t; s++) mx = fmaxf(mx, p[t][s]);
        float sum = 0.f;
        for (int s = 0; s <= t; s++) { float e = expf(p[t][s] - mx); p[t][s] = e; sum += e; }
        float inv = 1.f / sum;
        for (int s = 0; s <= t; s++) p[t][s] *= inv;
        for (int s = t + 1; s < SEQT; s++) p[t][s] = 0.f;
    }
    __syncthreads();

    for (int idx = tid; idx < SEQT * HEADD; idx += 256) {
        int t = idx / HEADD, d = idx % HEADD;
        float acc = 0.f;
        for (int s = 0; s <= t; s++) acc += p[t][s] * v[s][d];
        size_t off = (size_t)(bidx * SEQT + t) * 256 + hh * HEADD + d;
        __half yh, yl; split1h(acc, yh, yl);
        oh[off] = yh; ol[off] = yl;
    }
}

// ---------------------------------------------------------------------------
// Launch
// ---------------------------------------------------------------------------
extern "C" void kernel_launch(void* const* d_in, const int* in_sizes, int n_in,
                              void* d_out, int out_size)
{
    const float* x         = (const float*)d_in[0];
    const float* p1_w      = (const float*)d_in[1];
    const float* p1_b      = (const float*)d_in[2];
    const float* pln1_w    = (const float*)d_in[3];
    const float* pln1_b    = (const float*)d_in[4];
    const float* p2_w      = (const float*)d_in[5];
    const float* pln2_w    = (const float*)d_in[6];
    const float* pln2_b    = (const float*)d_in[7];
    const float* in_proj_w = (const float*)d_in[8];
    const float* in_proj_b = (const float*)d_in[9];
    const float* out_proj_w= (const float*)d_in[10];
    const float* out_proj_b= (const float*)d_in[11];
    const float* ln1_w     = (const float*)d_in[12];
    const float* ln1_b     = (const float*)d_in[13];
    const float* lin1_w    = (const float*)d_in[14];
    const float* lin1_b    = (const float*)d_in[15];
    const float* lin2_w    = (const float*)d_in[16];
    const float* lin2_b    = (const float*)d_in[17];
    const float* ln2_w     = (const float*)d_in[18];
    const float* ln2_b     = (const float*)d_in[19];
    const float* head_w    = (const float*)d_in[20];
    float* out = (float*)d_out;

    float *b1f, *b2f, *hf;
    __half *xh,*xl,*b1h,*b1l,*b2h,*b2l,*hh,*hl;
    __half *w1,*w2,*wq,*wo,*wf1,*wf2,*wn;
    cudaGetSymbolAddress((void**)&b1f, g_b1f);
    cudaGetSymbolAddress((void**)&b2f, g_b2f);
    cudaGetSymbolAddress((void**)&hf,  g_hf);
    cudaGetSymbolAddress((void**)&xh,  g_xh);  cudaGetSymbolAddress((void**)&xl,  g_xl);
    cudaGetSymbolAddress((void**)&b1h, g_b1h); cudaGetSymbolAddress((void**)&b1l, g_b1l);
    cudaGetSymbolAddress((void**)&b2h, g_b2h); cudaGetSymbolAddress((void**)&b2l, g_b2l);
    cudaGetSymbolAddress((void**)&hh,  g_hh);  cudaGetSymbolAddress((void**)&hl,  g_hl);
    cudaGetSymbolAddress((void**)&w1,  g_w1);  cudaGetSymbolAddress((void**)&w2,  g_w2);
    cudaGetSymbolAddress((void**)&wq,  g_wq);  cudaGetSymbolAddress((void**)&wo,  g_wo);
    cudaGetSymbolAddress((void**)&wf1, g_wf1); cudaGetSymbolAddress((void**)&wf2, g_wf2);
    cudaGetSymbolAddress((void**)&wn,  g_wn);

    cudaFuncSetAttribute(gemm_fp2<0>, cudaFuncAttributeMaxDynamicSharedMemorySize, SMEM_DYN);
    cudaFuncSetAttribute(gemm_fp2<1>, cudaFuncAttributeMaxDynamicSharedMemorySize, SMEM_DYN);
    cudaFuncSetAttribute(gemm_fp2<2>, cudaFuncAttributeMaxDynamicSharedMemorySize, SMEM_DYN);

    const int M = M_TOK;
    const dim3 blk(256);
    const int MB = M / 128;  // 320
    #define GRID(N_) dim3(((N_) + 127) / 128, MB)
    #define SPLITH(src, dh, dl, n) do { long n4 = (long)(n) / 4; \
        split_f32h<<<(unsigned)((n4 + 255) / 256), 256>>>(src, dh, dl, n4); } while (0)
    #define CONVH(src, dst, n) do { long n4 = (long)(n) / 4; \
        conv_f16<<<(unsigned)((n4 + 255) / 256), 256>>>(src, dst, n4); } while (0)

    // one-time conversions
    SPLITH(x, xh, xl, (long)M * 2048);
    CONVH(p1_w,  w1,  1024L * 2048);
    CONVH(p2_w,  w2,  256L * 1024);
    CONVH(in_proj_w, wq, 2L * 768 * 256);
    CONVH(out_proj_w, wo, 2L * 256 * 256);
    CONVH(lin1_w, wf1, 2L * 1024 * 256);
    CONVH(lin2_w, wf2, 2L * 256 * 1024);

    // projector
    gemm_fp2<0><<<GRID(1024), blk, SMEM_DYN>>>(xh, xl, w1, p1_b, b1f,
                                               nullptr, nullptr, M, 1024, 2048, 1.f);
    ln_gelu_1024<<<M, blk>>>(b1f, b1h, b1l, pln1_w, pln1_b);
    gemm_fp2<0><<<GRID(256), blk, SMEM_DYN>>>(b1h, b1l, w2, nullptr, b2f,
                                              nullptr, nullptr, M, 256, 1024, 1.f);
    ln_pe_256<<<M / 8, blk>>>(b2f, hf, hh, hl, pln2_w, pln2_b);

    // transformer layers
    for (int i = 0; i < NLAYER; i++) {
        const __half* iq  = wq  + (size_t)i * 768 * 256;
        const __half* io  = wo  + (size_t)i * 256 * 256;
        const __half* if1 = wf1 + (size_t)i * 1024 * 256;
        const __half* if2 = wf2 + (size_t)i * 256 * 1024;
        const float* ipb = in_proj_b + (size_t)i * 768;
        const float* opb = out_proj_b + (size_t)i * 256;
        const float* l1b = lin1_b + (size_t)i * 1024;
        const float* l2b = lin2_b + (size_t)i * 256;

        gemm_fp2<0><<<GRID(768), blk, SMEM_DYN>>>(hh, hl, iq, ipb, b1f,
                                                  nullptr, nullptr, M, 768, 256, 1.f);
        attn_kernel<<<BATCH * NHEAD, blk>>>(b1f, b2h, b2l);
        gemm_fp2<0><<<GRID(256), blk, SMEM_DYN>>>(b2h, b2l, io, opb, b2f,
                                                  nullptr, nullptr, M, 256, 256, 1.f);
        resln_256<<<M / 8, blk>>>(hf, b2f, hh, hl,
                                  ln1_w + (size_t)i * 256, ln1_b + (size_t)i * 256);
        gemm_fp2<1><<<GRID(1024), blk, SMEM_DYN>>>(hh, hl, if1, l1b, nullptr,
                                                   b1h, b1l, M, 1024, 256, 1.f);
        gemm_fp2<0><<<GRID(256), blk, SMEM_DYN>>>(b1h, b1l, if2, l2b, b2f,
                                                  nullptr, nullptr, M, 256, 1024, 1.f);
        resln_256<<<M / 8, blk>>>(hf, b2f, hh, hl,
                                  ln2_w + (size_t)i * 256, ln2_b + (size_t)i * 256);
    }

    // cosine head: flat split hi/lo (A), wn single fp16 (W)
    norm_rows_256<<<M / 8, blk>>>(hf, b2h, b2l, M);
    norm_rows_256<<<(NCLS + 7) / 8, blk>>>(head_w, wn, nullptr, NCLS);
    gemm_fp2<2><<<GRID(NCLS), blk, SMEM_DYN>>>(b2h, b2l, wn, nullptr, out,
                                               nullptr, nullptr, M, NCLS, 256, 10.f);
}

// round 15
// speedup vs baseline: 1.3632x; 1.1005x over previous
#include <cuda_runtime.h>
#include <cuda_fp16.h>
#include <math.h>
#include <stdint.h>

// ---------------------------------------------------------------------------
// Problem constants
// ---------------------------------------------------------------------------
#define BATCH 2048
#define SEQT  20
#define M_TOK (BATCH*SEQT)   // 40960 tokens
#define NHEAD 4
#define HEADD 64
#define NCLS  1000
#define NLAYER 2

// ---------------------------------------------------------------------------
// Scratch
// ---------------------------------------------------------------------------
__device__ float g_b1f[(size_t)M_TOK * 1024];
__device__ float g_hf [(size_t)M_TOK * 256];

__device__ __half g_xh [(size_t)M_TOK * 2048];
__device__ __half g_b1h[(size_t)M_TOK * 1024];
__device__ __half g_b1l[(size_t)M_TOK * 1024];
__device__ __half g_b2h[(size_t)M_TOK * 256];
__device__ __half g_b2l[(size_t)M_TOK * 256];
__device__ __half g_hh [(size_t)M_TOK * 256];
__device__ __half g_hl [(size_t)M_TOK * 256];

__device__ __half g_w1 [1024*2048];
__device__ __half g_w2 [256*1024];
__device__ __half g_wq [2*768*256];
__device__ __half g_wo [2*256*256];
__device__ __half g_wf1[2*1024*256];
__device__ __half g_wf2[2*256*1024];
__device__ __half g_wn [NCLS*256];

// ---------------------------------------------------------------------------
// Helpers
// ---------------------------------------------------------------------------
__device__ __forceinline__ float geluf(float x) {
    return 0.5f * x * (1.0f + erff(x * 0.7071067811865475f));
}
__device__ __forceinline__ float warp_sum(float v) {
    #pragma unroll
    for (int o = 16; o; o >>= 1) v += __shfl_xor_sync(0xffffffffu, v, o);
    return v;
}
__device__ __forceinline__ uint32_t smem_u32(const void* p) {
    uint32_t a;
    asm("{ .reg .u64 t; cvta.to.shared.u64 t, %1; cvt.u32.u64 %0, t; }" : "=r"(a) : "l"(p));
    return a;
}
__device__ __forceinline__ void ldsm4(uint32_t (&r)[4], uint32_t addr) {
    asm volatile("ldmatrix.sync.aligned.m8n8.x4.shared.b16 {%0,%1,%2,%3}, [%4];"
                 : "=r"(r[0]), "=r"(r[1]), "=r"(r[2]), "=r"(r[3]) : "r"(addr));
}
__device__ __forceinline__ void mma16816h(float (&d)[4], const uint32_t (&a)[4],
                                          const uint32_t* b) {
    asm volatile("mma.sync.aligned.m16n8k16.row.col.f32.f16.f16.f32 "
                 "{%0,%1,%2,%3}, {%4,%5,%6,%7}, {%8,%9}, {%0,%1,%2,%3};"
                 : "+f"(d[0]), "+f"(d[1]), "+f"(d[2]), "+f"(d[3])
                 : "r"(a[0]), "r"(a[1]), "r"(a[2]), "r"(a[3]),
                   "r"(b[0]), "r"(b[1]));
}
__device__ __forceinline__ void cp16(uint32_t dst, const void* src, int sz) {
    asm volatile("cp.async.cg.shared.global [%0], [%1], 16, %2;"
                 :: "r"(dst), "l"(src), "r"(sz) : "memory");
}
#define CP_COMMIT()  asm volatile("cp.async.commit_group;" ::: "memory")
#define CP_WAIT1()   asm volatile("cp.async.wait_group 1;" ::: "memory")
#define CP_WAIT0()   asm volatile("cp.async.wait_group 0;" ::: "memory")

__device__ __forceinline__ void split1h(float x, __half& h, __half& l) {
    h = __float2half_rn(x);
    l = __float2half_rn(x - __half2float(h));
}

#define ROWB   80            // 64B data (32 fp16) + 16B pad

// ---------------------------------------------------------------------------
// Generic fp16 GEMM (TERMS=2: A ~ Ah+Al; TERMS=1: A ~ Ah only), W single fp16
//   EPI 0: fp32 +bias   EPI 1: gelu(+bias) -> fp16 hi/lo   EPI 2: fp32 *scale
// CTA 128x128, 256 thr, K-chunk 32, cp.async 2-stage ring, 2 CTAs/SM.
// ---------------------------------------------------------------------------
#define OFF_AH 0
#define OFF_AL 10240
#define OFF_WH 20480
#define STAGE  30720
#define SMEM_DYN (2*STAGE)   // 61440 -> 2 CTAs/SM

template<int EPI, int TERMS>
__global__ __launch_bounds__(256, 2)
void gemm_fp2(const __half* __restrict__ Ah, const __half* __restrict__ Al,
              const __half* __restrict__ Wh,
              const float* __restrict__ bias, float* __restrict__ Cf,
              __half* __restrict__ Ch, __half* __restrict__ Cl,
              int M, int N, int K, float scale)
{
    extern __shared__ __align__(128) char smem[];
    const uint32_t sb = smem_u32(smem);
    const int tid  = threadIdx.x;
    const int wid  = tid >> 5;
    const int lane = tid & 31;
    const int bm = blockIdx.y * 128;
    const int bn = blockIdx.x * 128;
    const int wm = (wid & 3) * 32;
    const int wn = (wid >> 2) * 64;

    float acc[2][8][4];
    #pragma unroll
    for (int mi = 0; mi < 2; mi++)
        #pragma unroll
        for (int ni = 0; ni < 8; ni++)
            #pragma unroll
            for (int e = 0; e < 4; e++) acc[mi][ni][e] = 0.f;

    const int r_ = tid >> 2;
    const int sg = tid & 3;
    auto issue = [&](int c) {
        const uint32_t st = sb + (c & 1) * STAGE;
        const size_t kb = (size_t)c * 64 + sg * 16;
        #pragma unroll
        for (int i = 0; i < 6; i++) {
            const int arr = i >> 1;                    // 0:Ah 1:Al 2:Wh
            if (TERMS == 1 && arr == 1) continue;
            const int r = r_ + ((i & 1) << 6);
            const uint32_t dst = st + arr * 10240 + r * ROWB + sg * 16;
            const __half* base;
            int row, sz = 16;
            if (arr < 2) { base = (arr == 0) ? Ah : Al; row = bm + r; }
            else {
                int gn = bn + r;
                if (gn >= N) { gn = N - 1; sz = 0; }
                base = Wh; row = gn;
            }
            cp16(dst, (const char*)base + (size_t)row * K * 2 + kb, sz);
        }
    };

    const uint32_t a_row = wm + (lane & 15);
    const uint32_t a_kof = (lane >> 4) << 3;
    const uint32_t b_row = wn + (lane & 7) + (((lane >> 4) & 1) << 3);
    const uint32_t b_kof = ((lane >> 3) & 1) << 3;

    auto mma_chunk = [&](uint32_t st) {
        #pragma unroll
        for (int ks = 0; ks < 2; ks++) {
            const uint32_t k0 = ks << 4;
            uint32_t ah_[2][4], al_[2][4];
            #pragma unroll
            for (int mi = 0; mi < 2; mi++) {
                ldsm4(ah_[mi], st + OFF_AH + (a_row + mi*16) * ROWB + (k0 + a_kof) * 2);
                if (TERMS == 2)
                    ldsm4(al_[mi], st + OFF_AL + (a_row + mi*16) * ROWB + (k0 + a_kof) * 2);
            }
            uint32_t bh_[8][2];
            #pragma unroll
            for (int nj = 0; nj < 4; nj++) {
                uint32_t r[4];
                ldsm4(r, st + OFF_WH + (b_row + nj*16) * ROWB + (k0 + b_kof) * 2);
                bh_[2*nj][0] = r[0]; bh_[2*nj][1] = r[1];
                bh_[2*nj+1][0] = r[2]; bh_[2*nj+1][1] = r[3];
            }
            #pragma unroll
            for (int mi = 0; mi < 2; mi++)
                #pragma unroll
                for (int ni = 0; ni < 8; ni++) {
                    mma16816h(acc[mi][ni], ah_[mi], bh_[ni]);
                    if (TERMS == 2) mma16816h(acc[mi][ni], al_[mi], bh_[ni]);
                }
        }
    };

    const int nch = K >> 5;
    issue(0); CP_COMMIT();
    for (int c = 0; c < nch; c++) {
        if (c + 1 < nch) { issue(c + 1); CP_COMMIT(); CP_WAIT1(); }
        else             { CP_WAIT0(); }
        __syncthreads();
        mma_chunk(sb + (c & 1) * STAGE);
        __syncthreads();
    }

    const int r0 = lane >> 2;
    const int cc0 = (lane & 3) << 1;
    #pragma unroll
    for (int mi = 0; mi < 2; mi++) {
        #pragma unroll
        for (int ni = 0; ni < 8; ni++) {
            int col = bn + wn + ni * 8 + cc0;
            if (col >= N) continue;
            float b0 = 0.f, b1 = 0.f;
            if (EPI != 2 && bias != nullptr) { b0 = bias[col]; b1 = bias[col + 1]; }
            int row = bm + wm + mi * 16 + r0;
            #pragma unroll
            for (int hh = 0; hh < 2; hh++) {
                float t0 = acc[mi][ni][2*hh + 0] + b0;
                float t1 = acc[mi][ni][2*hh + 1] + b1;
                size_t off = (size_t)(row + 8*hh) * N + col;
                if (EPI == 1) {
                    t0 = geluf(t0); t1 = geluf(t1);
                    __half h0, l0, h1, l1;
                    split1h(t0, h0, l0); split1h(t1, h1, l1);
                    *(__half2*)(Ch + off) = __halves2half2(h0, h1);
                    *(__half2*)(Cl + off) = __halves2half2(l0, l1);
                } else {
                    if (EPI == 2) { t0 *= scale; t1 *= scale; }
                    float2 o; o.x = t0; o.y = t1;
                    *(float2*)(Cf + off) = o;
                }
            }
        }
    }
}

// ---------------------------------------------------------------------------
// Fused GEMM + LayerNorm for N=256 (CTA owns full rows). 512 thr, 16 warps
// (4M x 4N), CTA tile 128x256, warp 32x64, 2-term A. 1 CTA/SM.
//   MODE 0: y = LN(acc) + PE         (p2: no bias, no resid)
//   MODE 1: y = LN(acc + bias + hres)  (out_proj / ff2)
// Writes hf (fp32) + hh/hl (fp16 split).
// ---------------------------------------------------------------------------
#define L_OFF_AH 0
#define L_OFF_AL 10240
#define L_OFF_W  20480
#define L_STAGE  40960
#define L_SMEM   (2*L_STAGE)   // 81920

template<int MODE>
__global__ __launch_bounds__(512, 1)
void gemm_ln256(const __half* __restrict__ Ah, const __half* __restrict__ Al,
                const __half* __restrict__ Wh,
                const float* __restrict__ bias, const float* __restrict__ hres,
                const float* __restrict__ lnw, const float* __restrict__ lnb,
                float* __restrict__ hf, __half* __restrict__ hh_, __half* __restrict__ hl_,
                int M, int K)
{
    extern __shared__ __align__(128) char smem[];
    const uint32_t sb = smem_u32(smem);
    const int tid  = threadIdx.x;
    const int wid  = tid >> 5;
    const int lane = tid & 31;
    const int bm = blockIdx.y * 128;
    const int wm = (wid & 3) * 32;
    const int wn = (wid >> 2) * 64;

    float acc[2][8][4];
    #pragma unroll
    for (int mi = 0; mi < 2; mi++)
        #pragma unroll
        for (int ni = 0; ni < 8; ni++)
            #pragma unroll
            for (int e = 0; e < 4; e++) acc[mi][ni][e] = 0.f;

    // cp.async: 512 rows-of-64B per chunk (Ah 128, Al 128, W 256), 4 per thread
    const int r_ = tid >> 2;   // 0..127
    const int sg = tid & 3;
    auto issue = [&](int c) {
        const uint32_t st = sb + (c & 1) * L_STAGE;
        const size_t kb = (size_t)c * 64 + sg * 16;
        cp16(st + L_OFF_AH + r_ * ROWB + sg * 16,
             (const char*)Ah + (size_t)(bm + r_) * K * 2 + kb, 16);
        cp16(st + L_OFF_AL + r_ * ROWB + sg * 16,
             (const char*)Al + (size_t)(bm + r_) * K * 2 + kb, 16);
        cp16(st + L_OFF_W + r_ * ROWB + sg * 16,
             (const char*)Wh + (size_t)r_ * K * 2 + kb, 16);
        cp16(st + L_OFF_W + (r_ + 128) * ROWB + sg * 16,
             (const char*)Wh + (size_t)(r_ + 128) * K * 2 + kb, 16);
    };

    const uint32_t a_row = wm + (lane & 15);
    const uint32_t a_kof = (lane >> 4) << 3;
    const uint32_t b_row = wn + (lane & 7) + (((lane >> 4) & 1) << 3);
    const uint32_t b_kof = ((lane >> 3) & 1) << 3;

    auto mma_chunk = [&](uint32_t st) {
        #pragma unroll
        for (int ks = 0; ks < 2; ks++) {
            const uint32_t k0 = ks << 4;
            uint32_t ah_[2][4], al_[2][4];
            #pragma unroll
            for (int mi = 0; mi < 2; mi++) {
                ldsm4(ah_[mi], st + L_OFF_AH + (a_row + mi*16) * ROWB + (k0 + a_kof) * 2);
                ldsm4(al_[mi], st + L_OFF_AL + (a_row + mi*16) * ROWB + (k0 + a_kof) * 2);
            }
            uint32_t bh_[8][2];
            #pragma unroll
            for (int nj = 0; nj < 4; nj++) {
                uint32_t r[4];
                ldsm4(r, st + L_OFF_W + (b_row + nj*16) * ROWB + (k0 + b_kof) * 2);
                bh_[2*nj][0] = r[0]; bh_[2*nj][1] = r[1];
                bh_[2*nj+1][0] = r[2]; bh_[2*nj+1][1] = r[3];
            }
            #pragma unroll
            for (int mi = 0; mi < 2; mi++)
                #pragma unroll
                for (int ni = 0; ni < 8; ni++) {
                    mma16816h(acc[mi][ni], ah_[mi], bh_[ni]);
                    mma16816h(acc[mi][ni], al_[mi], bh_[ni]);
                }
        }
    };

    const int nch = K >> 5;
    issue(0); CP_COMMIT();
    for (int c = 0; c < nch; c++) {
        if (c + 1 < nch) { issue(c + 1); CP_COMMIT(); CP_WAIT1(); }
        else             { CP_WAIT0(); }
        __syncthreads();
        mma_chunk(sb + (c & 1) * L_STAGE);
        __syncthreads();
    }

    // ---- epilogue: v = acc (+bias +resid); row-LN over 256 cols ----
    const int r0 = lane >> 2;
    const int cc0 = (lane & 3) << 1;
    const int wnidx = wid >> 2;          // which N-quarter
    float* rsum = (float*)smem;          // [128][4]
    float* rss  = rsum + 128 * 4;        // [128][4]

    float psum[2][2], pss[2][2];
    #pragma unroll
    for (int mi = 0; mi < 2; mi++)
        #pragma unroll
        for (int hh = 0; hh < 2; hh++) { psum[mi][hh] = 0.f; pss[mi][hh] = 0.f; }

    #pragma unroll
    for (int ni = 0; ni < 8; ni++) {
        int col = wn + ni * 8 + cc0;
        float b0 = 0.f, b1 = 0.f;
        if (MODE == 1) { b0 = bias[col]; b1 = bias[col + 1]; }
        #pragma unroll
        for (int mi = 0; mi < 2; mi++) {
            #pragma unroll
            for (int hh = 0; hh < 2; hh++) {
                int row = bm + wm + mi * 16 + r0 + 8 * hh;
                float t0 = acc[mi][ni][2*hh + 0] + b0;
                float t1 = acc[mi][ni][2*hh + 1] + b1;
                if (MODE == 1) {
                    float2 rr = *(const float2*)(hres + (size_t)row * 256 + col);
                    t0 += rr.x; t1 += rr.y;
                }
                acc[mi][ni][2*hh + 0] = t0;
                acc[mi][ni][2*hh + 1] = t1;
                psum[mi][hh] += t0 + t1;
                pss[mi][hh]  += t0 * t0 + t1 * t1;
            }
        }
    }
    // reduce over quad lanes (cols within this N-warp)
    #pragma unroll
    for (int mi = 0; mi < 2; mi++)
        #pragma unroll
        for (int hh = 0; hh < 2; hh++) {
            #pragma unroll
            for (int o = 1; o <= 2; o <<= 1) {
                psum[mi][hh] += __shfl_xor_sync(0xffffffffu, psum[mi][hh], o);
                pss[mi][hh]  += __shfl_xor_sync(0xffffffffu, pss[mi][hh], o);
            }
        }
    if ((lane & 3) == 0) {
        #pragma unroll
        for (int mi = 0; mi < 2; mi++)
            #pragma unroll
            for (int hh = 0; hh < 2; hh++) {
                int rl = wm + mi * 16 + r0 + 8 * hh;   // 0..127
                rsum[rl * 4 + wnidx] = psum[mi][hh];
                rss [rl * 4 + wnidx] = pss[mi][hh];
            }
    }
    __syncthreads();

    float mean[2][2], rstd[2][2];
    #pragma unroll
    for (int mi = 0; mi < 2; mi++)
        #pragma unroll
        for (int hh = 0; hh < 2; hh++) {
            int rl = wm + mi * 16 + r0 + 8 * hh;
            float s = rsum[rl*4+0] + rsum[rl*4+1] + rsum[rl*4+2] + rsum[rl*4+3];
            float q = rss [rl*4+0] + rss [rl*4+1] + rss [rl*4+2] + rss [rl*4+3];
            float m = s * (1.f / 256.f);
            float v = q * (1.f / 256.f) - m * m;
            mean[mi][hh] = m;
            rstd[mi][hh] = rsqrtf(v + 1e-6f);
        }

    #pragma unroll
    for (int ni = 0; ni < 8; ni++) {
        int col = wn + ni * 8 + cc0;
        float w0 = lnw[col], w1 = lnw[col + 1];
        float g0 = lnb[col], g1 = lnb[col + 1];
        #pragma unroll
        for (int mi = 0; mi < 2; mi++) {
            #pragma unroll
            for (int hh = 0; hh < 2; hh++) {
                int row = bm + wm + mi * 16 + r0 + 8 * hh;
                float y0 = (acc[mi][ni][2*hh+0] - mean[mi][hh]) * rstd[mi][hh] * w0 + g0;
                float y1 = (acc[mi][ni][2*hh+1] - mean[mi][hh]) * rstd[mi][hh] * w1 + g1;
                if (MODE == 0) {
                    int t = row % SEQT;
                    float ang = (float)t * expf((float)col * (-9.210340371976184f / 256.f));
                    y0 += sinf(ang);
                    y1 += cosf(ang);
                }
                size_t off = (size_t)row * 256 + col;
                float2 o; o.x = y0; o.y = y1;
                *(float2*)(hf + off) = o;
                __half h0, l0, h1, l1;
                split1h(y0, h0, l0); split1h(y1, h1, l1);
                *(__half2*)(hh_ + off) = __halves2half2(h0, h1);
                *(__half2*)(hl_ + off) = __halves2half2(l0, l1);
            }
        }
    }
}

// ---------------------------------------------------------------------------
// Small kernels
// ---------------------------------------------------------------------------
__global__ void conv_f16(const float* __restrict__ src, __half* __restrict__ dst, long n4)
{
    long i = (long)blockIdx.x * blockDim.x + threadIdx.x;
    if (i >= n4) return;
    float4 v = ((const float4*)src)[i];
    __half2 a = __floats2half2_rn(v.x, v.y);
    __half2 b = __floats2half2_rn(v.z, v.w);
    uint2 u; u.x = *(uint32_t*)&a; u.y = *(uint32_t*)&b;
    ((uint2*)dst)[i] = u;
}

__global__ void ln_gelu_1024(const float* __restrict__ buf,
                             __half* __restrict__ dh, __half* __restrict__ dl,
                             const float* __restrict__ w, const float* __restrict__ b)
{
    int row = blockIdx.x;
    const float4* p = (const float4*)(buf + (size_t)row * 1024);
    int tid = threadIdx.x;
    float4 x = p[tid];
    float s  = x.x + x.y + x.z + x.w;
    float ss = x.x*x.x + x.y*x.y + x.z*x.z + x.w*x.w;
    __shared__ float sh[2][8];
    float ws_ = warp_sum(s), wss = warp_sum(ss);
    if ((tid & 31) == 0) { sh[0][tid >> 5] = ws_; sh[1][tid >> 5] = wss; }
    __syncthreads();
    float tot = 0.f, tot2 = 0.f;
    #pragma unroll
    for (int i = 0; i < 8; i++) { tot += sh[0][i]; tot2 += sh[1][i]; }
    float mean = tot * (1.f / 1024.f);
    float var  = tot2 * (1.f / 1024.f) - mean * mean;
    float rstd = rsqrtf(var + 1e-6f);
    float4 wv = ((const float4*)w)[tid];
    float4 bv = ((const float4*)b)[tid];
    float y0 = geluf((x.x - mean) * rstd * wv.x + bv.x);
    float y1 = geluf((x.y - mean) * rstd * wv.y + bv.y);
    float y2 = geluf((x.z - mean) * rstd * wv.z + bv.z);
    float y3 = geluf((x.w - mean) * rstd * wv.w + bv.w);
    __half h0,l0,h1,l1,h2,l2,h3,l3;
    split1h(y0,h0,l0); split1h(y1,h1,l1); split1h(y2,h2,l2); split1h(y3,h3,l3);
    __half2 H01 = __halves2half2(h0,h1), H23 = __halves2half2(h2,h3);
    __half2 L01 = __halves2half2(l0,l1), L23 = __halves2half2(l2,l3);
    uint2 hu; hu.x = *(uint32_t*)&H01; hu.y = *(uint32_t*)&H23;
    uint2 lu; lu.x = *(uint32_t*)&L01; lu.y = *(uint32_t*)&L23;
    ((uint2*)(dh + (size_t)row * 1024))[tid] = hu;
    ((uint2*)(dl + (size_t)row * 1024))[tid] = lu;
}

__global__ void norm_rows_256(const float* __restrict__ src,
                              __half* __restrict__ oh, __half* __restrict__ ol,
                              int nrows)
{
    int row  = blockIdx.x * 8 + (threadIdx.x >> 5);
    int lane = threadIdx.x & 31;
    if (row >= nrows) return;
    const float* x = src + (size_t)row * 256;
    float v[8], ss = 0.f;
    #pragma unroll
    for (int i = 0; i < 8; i++) { v[i] = x[lane + 32*i]; ss += v[i]*v[i]; }
    ss = warp_sum(ss);
    float inv = 1.f / fmaxf(sqrtf(ss), 1e-12f);
    size_t base = (size_t)row * 256;
    #pragma unroll
    for (int i = 0; i < 8; i++) {
        int c = lane + 32*i;
        float y = v[i] * inv;
        __half yh, yl; split1h(y, yh, yl);
        oh[base + c] = yh;
        if (ol) ol[base + c] = yl;
    }
}

__global__ void attn_kernel(const float* __restrict__ qkv,
                            __half* __restrict__ oh, __half* __restrict__ ol)
{
    int bh = blockIdx.x;
    int bidx = bh / NHEAD;
    int hh   = bh % NHEAD;
    __shared__ float q[SEQT][HEADD];
    __shared__ float k[SEQT][HEADD];
    __shared__ float v[SEQT][HEADD];
    __shared__ float p[SEQT][SEQT];
    int tid = threadIdx.x;

    for (int idx = tid; idx < SEQT * HEADD; idx += 256) {
        int t = idx / HEADD, d = idx % HEADD;
        size_t off = (size_t)(bidx * SEQT + t) * 768 + hh * HEADD + d;
        q[t][d] = qkv[off];
        k[t][d] = qkv[off + 256];
        v[t][d] = qkv[off + 512];
    }
    __syncthreads();

    for (int idx = tid; idx < SEQT * SEQT; idx += 256) {
        int t = idx / SEQT, s = idx % SEQT;
        if (s <= t) {
            float acc = 0.f;
            #pragma unroll
            for (int d = 0; d < HEADD; d++) acc += q[t][d] * k[s][d];
            p[t][s] = acc * 0.125f;
        } else p[t][s] = 0.f;
    }
    __syncthreads();

    if (tid < SEQT) {
        int t = tid;
        float mx = -1e30f;
        for (int s = 0; s <= t; s++) mx = fmaxf(mx, p[t][s]);
        float sum = 0.f;
        for (int s = 0; s <= t; s++) { float e = expf(p[t][s] - mx); p[t][s] = e; sum += e; }
        float inv = 1.f / sum;
        for (int s = 0; s <= t; s++) p[t][s] *= inv;
        for (int s = t + 1; s < SEQT; s++) p[t][s] = 0.f;
    }
    __syncthreads();

    for (int idx = tid; idx < SEQT * HEADD; idx += 256) {
        int t = idx / HEADD, d = idx % HEADD;
        float acc = 0.f;
        for (int s = 0; s <= t; s++) acc += p[t][s] * v[s][d];
        size_t off = (size_t)(bidx * SEQT + t) * 256 + hh * HEADD + d;
        __half yh, yl; split1h(acc, yh, yl);
        oh[off] = yh; ol[off] = yl;
    }
}

// ---------------------------------------------------------------------------
// Launch
// ---------------------------------------------------------------------------
extern "C" void kernel_launch(void* const* d_in, const int* in_sizes, int n_in,
                              void* d_out, int out_size)
{
    const float* x         = (const float*)d_in[0];
    const float* p1_w      = (const float*)d_in[1];
    const float* p1_b      = (const float*)d_in[2];
    const float* pln1_w    = (const float*)d_in[3];
    const float* pln1_b    = (const float*)d_in[4];
    const float* p2_w      = (const float*)d_in[5];
    const float* pln2_w    = (const float*)d_in[6];
    const float* pln2_b    = (const float*)d_in[7];
    const float* in_proj_w = (const float*)d_in[8];
    const float* in_proj_b = (const float*)d_in[9];
    const float* out_proj_w= (const float*)d_in[10];
    const float* out_proj_b= (const float*)d_in[11];
    const float* ln1_w     = (const float*)d_in[12];
    const float* ln1_b     = (const float*)d_in[13];
    const float* lin1_w    = (const float*)d_in[14];
    const float* lin1_b    = (const float*)d_in[15];
    const float* lin2_w    = (const float*)d_in[16];
    const float* lin2_b    = (const float*)d_in[17];
    const float* ln2_w     = (const float*)d_in[18];
    const float* ln2_b     = (const float*)d_in[19];
    const float* head_w    = (const float*)d_in[20];
    float* out = (float*)d_out;

    float *b1f, *hf;
    __half *xh,*b1h,*b1l,*b2h,*b2l,*hh,*hl;
    __half *w1,*w2,*wq,*wo,*wf1,*wf2,*wn;
    cudaGetSymbolAddress((void**)&b1f, g_b1f);
    cudaGetSymbolAddress((void**)&hf,  g_hf);
    cudaGetSymbolAddress((void**)&xh,  g_xh);
    cudaGetSymbolAddress((void**)&b1h, g_b1h); cudaGetSymbolAddress((void**)&b1l, g_b1l);
    cudaGetSymbolAddress((void**)&b2h, g_b2h); cudaGetSymbolAddress((void**)&b2l, g_b2l);
    cudaGetSymbolAddress((void**)&hh,  g_hh);  cudaGetSymbolAddress((void**)&hl,  g_hl);
    cudaGetSymbolAddress((void**)&w1,  g_w1);  cudaGetSymbolAddress((void**)&w2,  g_w2);
    cudaGetSymbolAddress((void**)&wq,  g_wq);  cudaGetSymbolAddress((void**)&wo,  g_wo);
    cudaGetSymbolAddress((void**)&wf1, g_wf1); cudaGetSymbolAddress((void**)&wf2, g_wf2);
    cudaGetSymbolAddress((void**)&wn,  g_wn);

    cudaFuncSetAttribute(gemm_fp2<0,1>, cudaFuncAttributeMaxDynamicSharedMemorySize, SMEM_DYN);
    cudaFuncSetAttribute(gemm_fp2<0,2>, cudaFuncAttributeMaxDynamicSharedMemorySize, SMEM_DYN);
    cudaFuncSetAttribute(gemm_fp2<1,2>, cudaFuncAttributeMaxDynamicSharedMemorySize, SMEM_DYN);
    cudaFuncSetAttribute(gemm_fp2<2,2>, cudaFuncAttributeMaxDynamicSharedMemorySize, SMEM_DYN);
    cudaFuncSetAttribute(gemm_ln256<0>, cudaFuncAttributeMaxDynamicSharedMemorySize, L_SMEM);
    cudaFuncSetAttribute(gemm_ln256<1>, cudaFuncAttributeMaxDynamicSharedMemorySize, L_SMEM);

    const int M = M_TOK;
    const dim3 blk(256);
    const dim3 blk5(512);
    const int MB = M / 128;  // 320
    #define GRID(N_) dim3(((N_) + 127) / 128, MB)
    #define CONVH(src, dst, n) do { long n4 = (long)(n) / 4; \
        conv_f16<<<(unsigned)((n4 + 255) / 256), 256>>>(src, dst, n4); } while (0)

    // one-time conversions
    CONVH(x, xh, (long)M * 2048);
    CONVH(p1_w,  w1,  1024L * 2048);
    CONVH(p2_w,  w2,  256L * 1024);
    CONVH(in_proj_w, wq, 2L * 768 * 256);
    CONVH(out_proj_w, wo, 2L * 256 * 256);
    CONVH(lin1_w, wf1, 2L * 1024 * 256);
    CONVH(lin2_w, wf2, 2L * 256 * 1024);

    // projector: p1 single-term fp16, then LN+GELU, then fused p2+LN+PE
    gemm_fp2<0,1><<<GRID(1024), blk, SMEM_DYN>>>(xh, nullptr, w1, p1_b, b1f,
                                                 nullptr, nullptr, M, 1024, 2048, 1.f);
    ln_gelu_1024<<<M, blk>>>(b1f, b1h, b1l, pln1_w, pln1_b);
    gemm_ln256<0><<<dim3(1, MB), blk5, L_SMEM>>>(b1h, b1l, w2, nullptr, nullptr,
                                                 pln2_w, pln2_b, hf, hh, hl, M, 1024);

    // transformer layers
    for (int i = 0; i < NLAYER; i++) {
        const __half* iq  = wq  + (size_t)i * 768 * 256;
        const __half* io  = wo  + (size_t)i * 256 * 256;
        const __half* if1 = wf1 + (size_t)i * 1024 * 256;
        const __half* if2 = wf2 + (size_t)i * 256 * 1024;
        const float* ipb = in_proj_b + (size_t)i * 768;
        const float* opb = out_proj_b + (size_t)i * 256;
        const float* l1b = lin1_b + (size_t)i * 1024;
        const float* l2b = lin2_b + (size_t)i * 256;

        gemm_fp2<0,2><<<GRID(768), blk, SMEM_DYN>>>(hh, hl, iq, ipb, b1f,
                                                    nullptr, nullptr, M, 768, 256, 1.f);
        attn_kernel<<<BATCH * NHEAD, blk>>>(b1f, b2h, b2l);
        gemm_ln256<1><<<dim3(1, MB), blk5, L_SMEM>>>(b2h, b2l, io, opb, hf,
                                                     ln1_w + (size_t)i * 256,
                                                     ln1_b + (size_t)i * 256,
                                                     hf, hh, hl, M, 256);
        gemm_fp2<1,2><<<GRID(1024), blk, SMEM_DYN>>>(hh, hl, if1, l1b, nullptr,
                                                     b1h, b1l, M, 1024, 256, 1.f);
        gemm_ln256<1><<<dim3(1, MB), blk5, L_SMEM>>>(b1h, b1l, if2, l2b, hf,
                                                     ln2_w + (size_t)i * 256,
                                                     ln2_b + (size_t)i * 256,
                                                     hf, hh, hl, M, 1024);
    }

    // cosine head
    norm_rows_256<<<M / 8, blk>>>(hf, b2h, b2l, M);
    norm_rows_256<<<(NCLS + 7) / 8, blk>>>(head_w, wn, nullptr, NCLS);
    gemm_fp2<2,2><<<GRID(NCLS), blk, SMEM_DYN>>>(b2h, b2l, wn, nullptr, out,
                                                 nullptr, nullptr, M, NCLS, 256, 10.f);
}

// round 16
// speedup vs baseline: 1.7223x; 1.2634x over previous
#include <cuda_runtime.h>
#include <cuda_fp16.h>
#include <math.h>
#include <stdint.h>

// ---------------------------------------------------------------------------
// Problem constants
// ---------------------------------------------------------------------------
#define BATCH 2048
#define SEQT  20
#define M_TOK (BATCH*SEQT)   // 40960 tokens
#define NHEAD 4
#define HEADD 64
#define NCLS  1000
#define NLAYER 2

// ---------------------------------------------------------------------------
// Scratch (single-term fp16 operands everywhere)
// ---------------------------------------------------------------------------
__device__ float g_b1f[(size_t)M_TOK * 1024];
__device__ float g_hf [(size_t)M_TOK * 256];

__device__ __half g_xh [(size_t)M_TOK * 2048];
__device__ __half g_b1h[(size_t)M_TOK * 1024];
__device__ __half g_b2h[(size_t)M_TOK * 256];
__device__ __half g_hh [(size_t)M_TOK * 256];

__device__ __half g_w1 [1024*2048];
__device__ __half g_w2 [256*1024];
__device__ __half g_wq [2*768*256];
__device__ __half g_wo [2*256*256];
__device__ __half g_wf1[2*1024*256];
__device__ __half g_wf2[2*256*1024];
__device__ __half g_wn [NCLS*256];

// ---------------------------------------------------------------------------
// Helpers
// ---------------------------------------------------------------------------
__device__ __forceinline__ float geluf(float x) {
    return 0.5f * x * (1.0f + erff(x * 0.7071067811865475f));
}
__device__ __forceinline__ float warp_sum(float v) {
    #pragma unroll
    for (int o = 16; o; o >>= 1) v += __shfl_xor_sync(0xffffffffu, v, o);
    return v;
}
__device__ __forceinline__ uint32_t smem_u32(const void* p) {
    uint32_t a;
    asm("{ .reg .u64 t; cvta.to.shared.u64 t, %1; cvt.u32.u64 %0, t; }" : "=r"(a) : "l"(p));
    return a;
}
__device__ __forceinline__ void ldsm4(uint32_t (&r)[4], uint32_t addr) {
    asm volatile("ldmatrix.sync.aligned.m8n8.x4.shared.b16 {%0,%1,%2,%3}, [%4];"
                 : "=r"(r[0]), "=r"(r[1]), "=r"(r[2]), "=r"(r[3]) : "r"(addr));
}
__device__ __forceinline__ void mma16816h(float (&d)[4], const uint32_t (&a)[4],
                                          const uint32_t* b) {
    asm volatile("mma.sync.aligned.m16n8k16.row.col.f32.f16.f16.f32 "
                 "{%0,%1,%2,%3}, {%4,%5,%6,%7}, {%8,%9}, {%0,%1,%2,%3};"
                 : "+f"(d[0]), "+f"(d[1]), "+f"(d[2]), "+f"(d[3])
                 : "r"(a[0]), "r"(a[1]), "r"(a[2]), "r"(a[3]),
                   "r"(b[0]), "r"(b[1]));
}
__device__ __forceinline__ void cp16(uint32_t dst, const void* src, int sz) {
    asm volatile("cp.async.cg.shared.global [%0], [%1], 16, %2;"
                 :: "r"(dst), "l"(src), "r"(sz) : "memory");
}
#define CP_COMMIT()  asm volatile("cp.async.commit_group;" ::: "memory")
#define CP_WAIT1()   asm volatile("cp.async.wait_group 1;" ::: "memory")
#define CP_WAIT0()   asm volatile("cp.async.wait_group 0;" ::: "memory")

#define ROWB   80            // 64B data (32 fp16) + 16B pad

// ---------------------------------------------------------------------------
// Single-term fp16 GEMM: C = A@W^T (A, W fp16)
//   EPI 0: fp32 +bias   EPI 1: gelu(+bias) -> fp16   EPI 2: fp32 *scale
// CTA 128x128, 256 thr, K-chunk 32, cp.async 2-stage ring, 2 CTAs/SM.
// ---------------------------------------------------------------------------
#define OFF_AH 0
#define OFF_WH 10240
#define STAGE  20480
#define SMEM_DYN (2*STAGE)   // 40960 -> 2 CTAs/SM

template<int EPI>
__global__ __launch_bounds__(256, 2)
void gemm_fp1(const __half* __restrict__ Ah, const __half* __restrict__ Wh,
              const float* __restrict__ bias, float* __restrict__ Cf,
              __half* __restrict__ Ch,
              int M, int N, int K, float scale)
{
    extern __shared__ __align__(128) char smem[];
    const uint32_t sb = smem_u32(smem);
    const int tid  = threadIdx.x;
    const int wid  = tid >> 5;
    const int lane = tid & 31;
    const int bm = blockIdx.y * 128;
    const int bn = blockIdx.x * 128;
    const int wm = (wid & 3) * 32;
    const int wn = (wid >> 2) * 64;

    float acc[2][8][4];
    #pragma unroll
    for (int mi = 0; mi < 2; mi++)
        #pragma unroll
        for (int ni = 0; ni < 8; ni++)
            #pragma unroll
            for (int e = 0; e < 4; e++) acc[mi][ni][e] = 0.f;

    const int r_ = tid >> 2;
    const int sg = tid & 3;
    auto issue = [&](int c) {
        const uint32_t st = sb + (c & 1) * STAGE;
        const size_t kb = (size_t)c * 64 + sg * 16;
        #pragma unroll
        for (int i = 0; i < 4; i++) {
            const int arr = i >> 1;                    // 0:Ah 1:Wh
            const int r = r_ + ((i & 1) << 6);
            const uint32_t dst = st + arr * 10240 + r * ROWB + sg * 16;
            const __half* base;
            int row, sz = 16;
            if (arr == 0) { base = Ah; row = bm + r; }
            else {
                int gn = bn + r;
                if (gn >= N) { gn = N - 1; sz = 0; }
                base = Wh; row = gn;
            }
            cp16(dst, (const char*)base + (size_t)row * K * 2 + kb, sz);
        }
    };

    const uint32_t a_row = wm + (lane & 15);
    const uint32_t a_kof = (lane >> 4) << 3;
    const uint32_t b_row = wn + (lane & 7) + (((lane >> 4) & 1) << 3);
    const uint32_t b_kof = ((lane >> 3) & 1) << 3;

    auto mma_chunk = [&](uint32_t st) {
        #pragma unroll
        for (int ks = 0; ks < 2; ks++) {
            const uint32_t k0 = ks << 4;
            uint32_t ah_[2][4];
            #pragma unroll
            for (int mi = 0; mi < 2; mi++)
                ldsm4(ah_[mi], st + OFF_AH + (a_row + mi*16) * ROWB + (k0 + a_kof) * 2);
            uint32_t bh_[8][2];
            #pragma unroll
            for (int nj = 0; nj < 4; nj++) {
                uint32_t r[4];
                ldsm4(r, st + OFF_WH + (b_row + nj*16) * ROWB + (k0 + b_kof) * 2);
                bh_[2*nj][0] = r[0]; bh_[2*nj][1] = r[1];
                bh_[2*nj+1][0] = r[2]; bh_[2*nj+1][1] = r[3];
            }
            #pragma unroll
            for (int mi = 0; mi < 2; mi++)
                #pragma unroll
                for (int ni = 0; ni < 8; ni++)
                    mma16816h(acc[mi][ni], ah_[mi], bh_[ni]);
        }
    };

    const int nch = K >> 5;
    issue(0); CP_COMMIT();
    for (int c = 0; c < nch; c++) {
        if (c + 1 < nch) { issue(c + 1); CP_COMMIT(); CP_WAIT1(); }
        else             { CP_WAIT0(); }
        __syncthreads();
        mma_chunk(sb + (c & 1) * STAGE);
        __syncthreads();
    }

    const int r0 = lane >> 2;
    const int cc0 = (lane & 3) << 1;
    #pragma unroll
    for (int mi = 0; mi < 2; mi++) {
        #pragma unroll
        for (int ni = 0; ni < 8; ni++) {
            int col = bn + wn + ni * 8 + cc0;
            if (col >= N) continue;
            float b0 = 0.f, b1 = 0.f;
            if (EPI != 2 && bias != nullptr) { b0 = bias[col]; b1 = bias[col + 1]; }
            int row = bm + wm + mi * 16 + r0;
            #pragma unroll
            for (int hh = 0; hh < 2; hh++) {
                float t0 = acc[mi][ni][2*hh + 0] + b0;
                float t1 = acc[mi][ni][2*hh + 1] + b1;
                size_t off = (size_t)(row + 8*hh) * N + col;
                if (EPI == 1) {
                    t0 = geluf(t0); t1 = geluf(t1);
                    *(__half2*)(Ch + off) = __floats2half2_rn(t0, t1);
                } else {
                    if (EPI == 2) { t0 *= scale; t1 *= scale; }
                    float2 o; o.x = t0; o.y = t1;
                    *(float2*)(Cf + off) = o;
                }
            }
        }
    }
}

// ---------------------------------------------------------------------------
// Fused GEMM + LayerNorm for N=256 (CTA owns full rows). 512 thr, 16 warps
// (4M x 4N), CTA tile 128x256, single-term A. 1 CTA/SM.
//   MODE 0: y = LN(acc) + PE            (p2)
//   MODE 1: y = LN(acc + bias + hres)   (out_proj / ff2)
// Writes hf (fp32) + hh (fp16).
// ---------------------------------------------------------------------------
#define L_OFF_A  0
#define L_OFF_W  10240
#define L_STAGE  30720
#define L_SMEM   (2*L_STAGE)   // 61440

template<int MODE>
__global__ __launch_bounds__(512, 1)
void gemm_ln256(const __half* __restrict__ Ah, const __half* __restrict__ Wh,
                const float* __restrict__ bias, const float* __restrict__ hres,
                const float* __restrict__ lnw, const float* __restrict__ lnb,
                float* __restrict__ hf, __half* __restrict__ hh_,
                int M, int K)
{
    extern __shared__ __align__(128) char smem[];
    const uint32_t sb = smem_u32(smem);
    const int tid  = threadIdx.x;
    const int wid  = tid >> 5;
    const int lane = tid & 31;
    const int bm = blockIdx.y * 128;
    const int wm = (wid & 3) * 32;
    const int wn = (wid >> 2) * 64;

    float acc[2][8][4];
    #pragma unroll
    for (int mi = 0; mi < 2; mi++)
        #pragma unroll
        for (int ni = 0; ni < 8; ni++)
            #pragma unroll
            for (int e = 0; e < 4; e++) acc[mi][ni][e] = 0.f;

    // cp.async: A 128 rows + W 256 rows of 64B per chunk = 3 x 16B per thread
    const int r_ = tid >> 2;   // 0..127
    const int sg = tid & 3;
    auto issue = [&](int c) {
        const uint32_t st = sb + (c & 1) * L_STAGE;
        const size_t kb = (size_t)c * 64 + sg * 16;
        cp16(st + L_OFF_A + r_ * ROWB + sg * 16,
             (const char*)Ah + (size_t)(bm + r_) * K * 2 + kb, 16);
        cp16(st + L_OFF_W + r_ * ROWB + sg * 16,
             (const char*)Wh + (size_t)r_ * K * 2 + kb, 16);
        cp16(st + L_OFF_W + (r_ + 128) * ROWB + sg * 16,
             (const char*)Wh + (size_t)(r_ + 128) * K * 2 + kb, 16);
    };

    const uint32_t a_row = wm + (lane & 15);
    const uint32_t a_kof = (lane >> 4) << 3;
    const uint32_t b_row = wn + (lane & 7) + (((lane >> 4) & 1) << 3);
    const uint32_t b_kof = ((lane >> 3) & 1) << 3;

    auto mma_chunk = [&](uint32_t st) {
        #pragma unroll
        for (int ks = 0; ks < 2; ks++) {
            const uint32_t k0 = ks << 4;
            uint32_t ah_[2][4];
            #pragma unroll
            for (int mi = 0; mi < 2; mi++)
                ldsm4(ah_[mi], st + L_OFF_A + (a_row + mi*16) * ROWB + (k0 + a_kof) * 2);
            uint32_t bh_[8][2];
            #pragma unroll
            for (int nj = 0; nj < 4; nj++) {
                uint32_t r[4];
                ldsm4(r, st + L_OFF_W + (b_row + nj*16) * ROWB + (k0 + b_kof) * 2);
                bh_[2*nj][0] = r[0]; bh_[2*nj][1] = r[1];
                bh_[2*nj+1][0] = r[2]; bh_[2*nj+1][1] = r[3];
            }
            #pragma unroll
            for (int mi = 0; mi < 2; mi++)
                #pragma unroll
                for (int ni = 0; ni < 8; ni++)
                    mma16816h(acc[mi][ni], ah_[mi], bh_[ni]);
        }
    };

    const int nch = K >> 5;
    issue(0); CP_COMMIT();
    for (int c = 0; c < nch; c++) {
        if (c + 1 < nch) { issue(c + 1); CP_COMMIT(); CP_WAIT1(); }
        else             { CP_WAIT0(); }
        __syncthreads();
        mma_chunk(sb + (c & 1) * L_STAGE);
        __syncthreads();
    }

    // ---- epilogue: v = acc (+bias +resid); row-LN over 256 cols ----
    const int r0 = lane >> 2;
    const int cc0 = (lane & 3) << 1;
    const int wnidx = wid >> 2;
    float* rsum = (float*)smem;          // [128][4]
    float* rss  = rsum + 128 * 4;        // [128][4]

    float psum[2][2], pss[2][2];
    #pragma unroll
    for (int mi = 0; mi < 2; mi++)
        #pragma unroll
        for (int hh = 0; hh < 2; hh++) { psum[mi][hh] = 0.f; pss[mi][hh] = 0.f; }

    #pragma unroll
    for (int ni = 0; ni < 8; ni++) {
        int col = wn + ni * 8 + cc0;
        float b0 = 0.f, b1 = 0.f;
        if (MODE == 1) { b0 = bias[col]; b1 = bias[col + 1]; }
        #pragma unroll
        for (int mi = 0; mi < 2; mi++) {
            #pragma unroll
            for (int hh = 0; hh < 2; hh++) {
                int row = bm + wm + mi * 16 + r0 + 8 * hh;
                float t0 = acc[mi][ni][2*hh + 0] + b0;
                float t1 = acc[mi][ni][2*hh + 1] + b1;
                if (MODE == 1) {
                    float2 rr = *(const float2*)(hres + (size_t)row * 256 + col);
                    t0 += rr.x; t1 += rr.y;
                }
                acc[mi][ni][2*hh + 0] = t0;
                acc[mi][ni][2*hh + 1] = t1;
                psum[mi][hh] += t0 + t1;
                pss[mi][hh]  += t0 * t0 + t1 * t1;
            }
        }
    }
    #pragma unroll
    for (int mi = 0; mi < 2; mi++)
        #pragma unroll
        for (int hh = 0; hh < 2; hh++) {
            #pragma unroll
            for (int o = 1; o <= 2; o <<= 1) {
                psum[mi][hh] += __shfl_xor_sync(0xffffffffu, psum[mi][hh], o);
                pss[mi][hh]  += __shfl_xor_sync(0xffffffffu, pss[mi][hh], o);
            }
        }
    if ((lane & 3) == 0) {
        #pragma unroll
        for (int mi = 0; mi < 2; mi++)
            #pragma unroll
            for (int hh = 0; hh < 2; hh++) {
                int rl = wm + mi * 16 + r0 + 8 * hh;
                rsum[rl * 4 + wnidx] = psum[mi][hh];
                rss [rl * 4 + wnidx] = pss[mi][hh];
            }
    }
    __syncthreads();

    float mean[2][2], rstd[2][2];
    #pragma unroll
    for (int mi = 0; mi < 2; mi++)
        #pragma unroll
        for (int hh = 0; hh < 2; hh++) {
            int rl = wm + mi * 16 + r0 + 8 * hh;
            float s = rsum[rl*4+0] + rsum[rl*4+1] + rsum[rl*4+2] + rsum[rl*4+3];
            float q = rss [rl*4+0] + rss [rl*4+1] + rss [rl*4+2] + rss [rl*4+3];
            float m = s * (1.f / 256.f);
            float v = q * (1.f / 256.f) - m * m;
            mean[mi][hh] = m;
            rstd[mi][hh] = rsqrtf(v + 1e-6f);
        }

    #pragma unroll
    for (int ni = 0; ni < 8; ni++) {
        int col = wn + ni * 8 + cc0;
        float w0 = lnw[col], w1 = lnw[col + 1];
        float g0 = lnb[col], g1 = lnb[col + 1];
        #pragma unroll
        for (int mi = 0; mi < 2; mi++) {
            #pragma unroll
            for (int hh = 0; hh < 2; hh++) {
                int row = bm + wm + mi * 16 + r0 + 8 * hh;
                float y0 = (acc[mi][ni][2*hh+0] - mean[mi][hh]) * rstd[mi][hh] * w0 + g0;
                float y1 = (acc[mi][ni][2*hh+1] - mean[mi][hh]) * rstd[mi][hh] * w1 + g1;
                if (MODE == 0) {
                    int t = row % SEQT;
                    float ang = (float)t * expf((float)col * (-9.210340371976184f / 256.f));
                    y0 += sinf(ang);
                    y1 += cosf(ang);
                }
                size_t off = (size_t)row * 256 + col;
                float2 o; o.x = y0; o.y = y1;
                *(float2*)(hf + off) = o;
                *(__half2*)(hh_ + off) = __floats2half2_rn(y0, y1);
            }
        }
    }
}

// ---------------------------------------------------------------------------
// Small kernels
// ---------------------------------------------------------------------------
__global__ void conv_f16(const float* __restrict__ src, __half* __restrict__ dst, long n4)
{
    long i = (long)blockIdx.x * blockDim.x + threadIdx.x;
    if (i >= n4) return;
    float4 v = ((const float4*)src)[i];
    __half2 a = __floats2half2_rn(v.x, v.y);
    __half2 b = __floats2half2_rn(v.z, v.w);
    uint2 u; u.x = *(uint32_t*)&a; u.y = *(uint32_t*)&b;
    ((uint2*)dst)[i] = u;
}

__global__ void ln_gelu_1024(const float* __restrict__ buf,
                             __half* __restrict__ dh,
                             const float* __restrict__ w, const float* __restrict__ b)
{
    int row = blockIdx.x;
    const float4* p = (const float4*)(buf + (size_t)row * 1024);
    int tid = threadIdx.x;
    float4 x = p[tid];
    float s  = x.x + x.y + x.z + x.w;
    float ss = x.x*x.x + x.y*x.y + x.z*x.z + x.w*x.w;
    __shared__ float sh[2][8];
    float ws_ = warp_sum(s), wss = warp_sum(ss);
    if ((tid & 31) == 0) { sh[0][tid >> 5] = ws_; sh[1][tid >> 5] = wss; }
    __syncthreads();
    float tot = 0.f, tot2 = 0.f;
    #pragma unroll
    for (int i = 0; i < 8; i++) { tot += sh[0][i]; tot2 += sh[1][i]; }
    float mean = tot * (1.f / 1024.f);
    float var  = tot2 * (1.f / 1024.f) - mean * mean;
    float rstd = rsqrtf(var + 1e-6f);
    float4 wv = ((const float4*)w)[tid];
    float4 bv = ((const float4*)b)[tid];
    float y0 = geluf((x.x - mean) * rstd * wv.x + bv.x);
    float y1 = geluf((x.y - mean) * rstd * wv.y + bv.y);
    float y2 = geluf((x.z - mean) * rstd * wv.z + bv.z);
    float y3 = geluf((x.w - mean) * rstd * wv.w + bv.w);
    __half2 H01 = __floats2half2_rn(y0, y1);
    __half2 H23 = __floats2half2_rn(y2, y3);
    uint2 hu; hu.x = *(uint32_t*)&H01; hu.y = *(uint32_t*)&H23;
    ((uint2*)(dh + (size_t)row * 1024))[tid] = hu;
}

__global__ void norm_rows_256(const float* __restrict__ src,
                              __half* __restrict__ oh, int nrows)
{
    int row  = blockIdx.x * 8 + (threadIdx.x >> 5);
    int lane = threadIdx.x & 31;
    if (row >= nrows) return;
    const float* x = src + (size_t)row * 256;
    float v[8], ss = 0.f;
    #pragma unroll
    for (int i = 0; i < 8; i++) { v[i] = x[lane + 32*i]; ss += v[i]*v[i]; }
    ss = warp_sum(ss);
    float inv = 1.f / fmaxf(sqrtf(ss), 1e-12f);
    size_t base = (size_t)row * 256;
    #pragma unroll
    for (int i = 0; i < 8; i++) {
        int c = lane + 32*i;
        oh[base + c] = __float2half_rn(v[i] * inv);
    }
}

__global__ void attn_kernel(const float* __restrict__ qkv, __half* __restrict__ oh)
{
    int bh = blockIdx.x;
    int bidx = bh / NHEAD;
    int hh   = bh % NHEAD;
    __shared__ float q[SEQT][HEADD];
    __shared__ float k[SEQT][HEADD];
    __shared__ float v[SEQT][HEADD];
    __shared__ float p[SEQT][SEQT];
    int tid = threadIdx.x;

    for (int idx = tid; idx < SEQT * HEADD; idx += 256) {
        int t = idx / HEADD, d = idx % HEADD;
        size_t off = (size_t)(bidx * SEQT + t) * 768 + hh * HEADD + d;
        q[t][d] = qkv[off];
        k[t][d] = qkv[off + 256];
        v[t][d] = qkv[off + 512];
    }
    __syncthreads();

    for (int idx = tid; idx < SEQT * SEQT; idx += 256) {
        int t = idx / SEQT, s = idx % SEQT;
        if (s <= t) {
            float acc = 0.f;
            #pragma unroll
            for (int d = 0; d < HEADD; d++) acc += q[t][d] * k[s][d];
            p[t][s] = acc * 0.125f;
        } else p[t][s] = 0.f;
    }
    __syncthreads();

    if (tid < SEQT) {
        int t = tid;
        float mx = -1e30f;
        for (int s = 0; s <= t; s++) mx = fmaxf(mx, p[t][s]);
        float sum = 0.f;
        for (int s = 0; s <= t; s++) { float e = expf(p[t][s] - mx); p[t][s] = e; sum += e; }
        float inv = 1.f / sum;
        for (int s = 0; s <= t; s++) p[t][s] *= inv;
        for (int s = t + 1; s < SEQT; s++) p[t][s] = 0.f;
    }
    __syncthreads();

    for (int idx = tid; idx < SEQT * HEADD; idx += 256) {
        int t = idx / HEADD, d = idx % HEADD;
        float acc = 0.f;
        for (int s = 0; s <= t; s++) acc += p[t][s] * v[s][d];
        size_t off = (size_t)(bidx * SEQT + t) * 256 + hh * HEADD + d;
        oh[off] = __float2half_rn(acc);
    }
}

// ---------------------------------------------------------------------------
// Launch
// ---------------------------------------------------------------------------
extern "C" void kernel_launch(void* const* d_in, const int* in_sizes, int n_in,
                              void* d_out, int out_size)
{
    const float* x         = (const float*)d_in[0];
    const float* p1_w      = (const float*)d_in[1];
    const float* p1_b      = (const float*)d_in[2];
    const float* pln1_w    = (const float*)d_in[3];
    const float* pln1_b    = (const float*)d_in[4];
    const float* p2_w      = (const float*)d_in[5];
    const float* pln2_w    = (const float*)d_in[6];
    const float* pln2_b    = (const float*)d_in[7];
    const float* in_proj_w = (const float*)d_in[8];
    const float* in_proj_b = (const float*)d_in[9];
    const float* out_proj_w= (const float*)d_in[10];
    const float* out_proj_b= (const float*)d_in[11];
    const float* ln1_w     = (const float*)d_in[12];
    const float* ln1_b     = (const float*)d_in[13];
    const float* lin1_w    = (const float*)d_in[14];
    const float* lin1_b    = (const float*)d_in[15];
    const float* lin2_w    = (const float*)d_in[16];
    const float* lin2_b    = (const float*)d_in[17];
    const float* ln2_w     = (const float*)d_in[18];
    const float* ln2_b     = (const float*)d_in[19];
    const float* head_w    = (const float*)d_in[20];
    float* out = (float*)d_out;

    float *b1f, *hf;
    __half *xh,*b1h,*b2h,*hh;
    __half *w1,*w2,*wq,*wo,*wf1,*wf2,*wn;
    cudaGetSymbolAddress((void**)&b1f, g_b1f);
    cudaGetSymbolAddress((void**)&hf,  g_hf);
    cudaGetSymbolAddress((void**)&xh,  g_xh);
    cudaGetSymbolAddress((void**)&b1h, g_b1h);
    cudaGetSymbolAddress((void**)&b2h, g_b2h);
    cudaGetSymbolAddress((void**)&hh,  g_hh);
    cudaGetSymbolAddress((void**)&w1,  g_w1);  cudaGetSymbolAddress((void**)&w2,  g_w2);
    cudaGetSymbolAddress((void**)&wq,  g_wq);  cudaGetSymbolAddress((void**)&wo,  g_wo);
    cudaGetSymbolAddress((void**)&wf1, g_wf1); cudaGetSymbolAddress((void**)&wf2, g_wf2);
    cudaGetSymbolAddress((void**)&wn,  g_wn);

    cudaFuncSetAttribute(gemm_fp1<0>, cudaFuncAttributeMaxDynamicSharedMemorySize, SMEM_DYN);
    cudaFuncSetAttribute(gemm_fp1<1>, cudaFuncAttributeMaxDynamicSharedMemorySize, SMEM_DYN);
    cudaFuncSetAttribute(gemm_fp1<2>, cudaFuncAttributeMaxDynamicSharedMemorySize, SMEM_DYN);
    cudaFuncSetAttribute(gemm_ln256<0>, cudaFuncAttributeMaxDynamicSharedMemorySize, L_SMEM);
    cudaFuncSetAttribute(gemm_ln256<1>, cudaFuncAttributeMaxDynamicSharedMemorySize, L_SMEM);

    const int M = M_TOK;
    const dim3 blk(256);
    const dim3 blk5(512);
    const int MB = M / 128;  // 320
    #define GRID(N_) dim3(((N_) + 127) / 128, MB)
    #define CONVH(src, dst, n) do { long n4 = (long)(n) / 4; \
        conv_f16<<<(unsigned)((n4 + 255) / 256), 256>>>(src, dst, n4); } while (0)

    // one-time conversions
    CONVH(x, xh, (long)M * 2048);
    CONVH(p1_w,  w1,  1024L * 2048);
    CONVH(p2_w,  w2,  256L * 1024);
    CONVH(in_proj_w, wq, 2L * 768 * 256);
    CONVH(out_proj_w, wo, 2L * 256 * 256);
    CONVH(lin1_w, wf1, 2L * 1024 * 256);
    CONVH(lin2_w, wf2, 2L * 256 * 1024);

    // projector
    gemm_fp1<0><<<GRID(1024), blk, SMEM_DYN>>>(xh, w1, p1_b, b1f, nullptr,
                                               M, 1024, 2048, 1.f);
    ln_gelu_1024<<<M, blk>>>(b1f, b1h, pln1_w, pln1_b);
    gemm_ln256<0><<<dim3(1, MB), blk5, L_SMEM>>>(b1h, w2, nullptr, nullptr,
                                                 pln2_w, pln2_b, hf, hh, M, 1024);

    // transformer layers
    for (int i = 0; i < NLAYER; i++) {
        const __half* iq  = wq  + (size_t)i * 768 * 256;
        const __half* io  = wo  + (size_t)i * 256 * 256;
        const __half* if1 = wf1 + (size_t)i * 1024 * 256;
        const __half* if2 = wf2 + (size_t)i * 256 * 1024;
        const float* ipb = in_proj_b + (size_t)i * 768;
        const float* opb = out_proj_b + (size_t)i * 256;
        const float* l1b = lin1_b + (size_t)i * 1024;
        const float* l2b = lin2_b + (size_t)i * 256;

        gemm_fp1<0><<<GRID(768), blk, SMEM_DYN>>>(hh, iq, ipb, b1f, nullptr,
                                                  M, 768, 256, 1.f);
        attn_kernel<<<BATCH * NHEAD, blk>>>(b1f, b2h);
        gemm_ln256<1><<<dim3(1, MB), blk5, L_SMEM>>>(b2h, io, opb, hf,
                                                     ln1_w + (size_t)i * 256,
                                                     ln1_b + (size_t)i * 256,
                                                     hf, hh, M, 256);
        gemm_fp1<1><<<GRID(1024), blk, SMEM_DYN>>>(hh, if1, l1b, nullptr, b1h,
                                                   M, 1024, 256, 1.f);
        gemm_ln256<1><<<dim3(1, MB), blk5, L_SMEM>>>(b1h, if2, l2b, hf,
                                                     ln2_w + (size_t)i * 256,
                                                     ln2_b + (size_t)i * 256,
                                                     hf, hh, M, 1024);
    }

    // cosine head
    norm_rows_256<<<M / 8, blk>>>(hf, b2h, M);
    norm_rows_256<<<(NCLS + 7) / 8, blk>>>(head_w, wn, NCLS);
    gemm_fp1<2><<<GRID(NCLS), blk, SMEM_DYN>>>(b2h, wn, nullptr, out, nullptr,
                                               M, NCLS, 256, 10.f);
}

// round 17
// speedup vs baseline: 1.7548x; 1.0189x over previous
#include <cuda_runtime.h>
#include <cuda_fp16.h>
#include <math.h>
#include <stdint.h>

// ---------------------------------------------------------------------------
// Problem constants
// ---------------------------------------------------------------------------
#define BATCH 2048
#define SEQT  20
#define M_TOK (BATCH*SEQT)   // 40960 tokens
#define NHEAD 4
#define HEADD 64
#define NCLS  1000
#define NLAYER 2

// ---------------------------------------------------------------------------
// Scratch (single-term fp16 operands everywhere)
// g_tmp: reused fp16 staging (p1-out M*1024, later qkv-out M*768)
// ---------------------------------------------------------------------------
__device__ __half g_tmp[(size_t)M_TOK * 1024];
__device__ float g_hf [(size_t)M_TOK * 256];

__device__ __half g_xh [(size_t)M_TOK * 2048];
__device__ __half g_b1h[(size_t)M_TOK * 1024];
__device__ __half g_b2h[(size_t)M_TOK * 256];
__device__ __half g_hh [(size_t)M_TOK * 256];

__device__ __half g_w1 [1024*2048];
__device__ __half g_w2 [256*1024];
__device__ __half g_wq [2*768*256];
__device__ __half g_wo [2*256*256];
__device__ __half g_wf1[2*1024*256];
__device__ __half g_wf2[2*256*1024];
__device__ __half g_wn [NCLS*256];

// ---------------------------------------------------------------------------
// Helpers
// ---------------------------------------------------------------------------
__device__ __forceinline__ float geluf(float x) {
    return 0.5f * x * (1.0f + erff(x * 0.7071067811865475f));
}
__device__ __forceinline__ float warp_sum(float v) {
    #pragma unroll
    for (int o = 16; o; o >>= 1) v += __shfl_xor_sync(0xffffffffu, v, o);
    return v;
}
__device__ __forceinline__ uint32_t smem_u32(const void* p) {
    uint32_t a;
    asm("{ .reg .u64 t; cvta.to.shared.u64 t, %1; cvt.u32.u64 %0, t; }" : "=r"(a) : "l"(p));
    return a;
}
__device__ __forceinline__ void ldsm4(uint32_t (&r)[4], uint32_t addr) {
    asm volatile("ldmatrix.sync.aligned.m8n8.x4.shared.b16 {%0,%1,%2,%3}, [%4];"
                 : "=r"(r[0]), "=r"(r[1]), "=r"(r[2]), "=r"(r[3]) : "r"(addr));
}
__device__ __forceinline__ void mma16816h(float (&d)[4], const uint32_t (&a)[4],
                                          const uint32_t* b) {
    asm volatile("mma.sync.aligned.m16n8k16.row.col.f32.f16.f16.f32 "
                 "{%0,%1,%2,%3}, {%4,%5,%6,%7}, {%8,%9}, {%0,%1,%2,%3};"
                 : "+f"(d[0]), "+f"(d[1]), "+f"(d[2]), "+f"(d[3])
                 : "r"(a[0]), "r"(a[1]), "r"(a[2]), "r"(a[3]),
                   "r"(b[0]), "r"(b[1]));
}
__device__ __forceinline__ void cp16(uint32_t dst, const void* src, int sz) {
    asm volatile("cp.async.cg.shared.global [%0], [%1], 16, %2;"
                 :: "r"(dst), "l"(src), "r"(sz) : "memory");
}
#define CP_COMMIT()  asm volatile("cp.async.commit_group;" ::: "memory")
#define CP_WAIT1()   asm volatile("cp.async.wait_group 1;" ::: "memory")
#define CP_WAIT0()   asm volatile("cp.async.wait_group 0;" ::: "memory")

#define ROWB   80            // 64B data (32 fp16) + 16B pad

// ---------------------------------------------------------------------------
// Single-term fp16 GEMM: C = A@W^T (A, W fp16)
//   EPI 0: fp32 +bias   EPI 1: gelu(+bias) -> fp16   EPI 2: fp32 *scale
//   EPI 3: +bias -> fp16
// CTA 128x128, 256 thr, K-chunk 32, cp.async 2-stage ring, 2 CTAs/SM.
// ---------------------------------------------------------------------------
#define OFF_AH 0
#define OFF_WH 10240
#define STAGE  20480
#define SMEM_DYN (2*STAGE)   // 40960 -> 2 CTAs/SM

template<int EPI>
__global__ __launch_bounds__(256, 2)
void gemm_fp1(const __half* __restrict__ Ah, const __half* __restrict__ Wh,
              const float* __restrict__ bias, float* __restrict__ Cf,
              __half* __restrict__ Ch,
              int M, int N, int K, float scale)
{
    extern __shared__ __align__(128) char smem[];
    const uint32_t sb = smem_u32(smem);
    const int tid  = threadIdx.x;
    const int wid  = tid >> 5;
    const int lane = tid & 31;
    const int bm = blockIdx.y * 128;
    const int bn = blockIdx.x * 128;
    const int wm = (wid & 3) * 32;
    const int wn = (wid >> 2) * 64;

    float acc[2][8][4];
    #pragma unroll
    for (int mi = 0; mi < 2; mi++)
        #pragma unroll
        for (int ni = 0; ni < 8; ni++)
            #pragma unroll
            for (int e = 0; e < 4; e++) acc[mi][ni][e] = 0.f;

    const int r_ = tid >> 2;
    const int sg = tid & 3;
    auto issue = [&](int c) {
        const uint32_t st = sb + (c & 1) * STAGE;
        const size_t kb = (size_t)c * 64 + sg * 16;
        #pragma unroll
        for (int i = 0; i < 4; i++) {
            const int arr = i >> 1;                    // 0:Ah 1:Wh
            const int r = r_ + ((i & 1) << 6);
            const uint32_t dst = st + arr * 10240 + r * ROWB + sg * 16;
            const __half* base;
            int row, sz = 16;
            if (arr == 0) { base = Ah; row = bm + r; }
            else {
                int gn = bn + r;
                if (gn >= N) { gn = N - 1; sz = 0; }
                base = Wh; row = gn;
            }
            cp16(dst, (const char*)base + (size_t)row * K * 2 + kb, sz);
        }
    };

    const uint32_t a_row = wm + (lane & 15);
    const uint32_t a_kof = (lane >> 4) << 3;
    const uint32_t b_row = wn + (lane & 7) + (((lane >> 4) & 1) << 3);
    const uint32_t b_kof = ((lane >> 3) & 1) << 3;

    auto mma_chunk = [&](uint32_t st) {
        #pragma unroll
        for (int ks = 0; ks < 2; ks++) {
            const uint32_t k0 = ks << 4;
            uint32_t ah_[2][4];
            #pragma unroll
            for (int mi = 0; mi < 2; mi++)
                ldsm4(ah_[mi], st + OFF_AH + (a_row + mi*16) * ROWB + (k0 + a_kof) * 2);
            uint32_t bh_[8][2];
            #pragma unroll
            for (int nj = 0; nj < 4; nj++) {
                uint32_t r[4];
                ldsm4(r, st + OFF_WH + (b_row + nj*16) * ROWB + (k0 + b_kof) * 2);
                bh_[2*nj][0] = r[0]; bh_[2*nj][1] = r[1];
                bh_[2*nj+1][0] = r[2]; bh_[2*nj+1][1] = r[3];
            }
            #pragma unroll
            for (int mi = 0; mi < 2; mi++)
                #pragma unroll
                for (int ni = 0; ni < 8; ni++)
                    mma16816h(acc[mi][ni], ah_[mi], bh_[ni]);
        }
    };

    const int nch = K >> 5;
    issue(0); CP_COMMIT();
    for (int c = 0; c < nch; c++) {
        if (c + 1 < nch) { issue(c + 1); CP_COMMIT(); CP_WAIT1(); }
        else             { CP_WAIT0(); }
        __syncthreads();
        mma_chunk(sb + (c & 1) * STAGE);
        __syncthreads();
    }

    const int r0 = lane >> 2;
    const int cc0 = (lane & 3) << 1;
    #pragma unroll
    for (int mi = 0; mi < 2; mi++) {
        #pragma unroll
        for (int ni = 0; ni < 8; ni++) {
            int col = bn + wn + ni * 8 + cc0;
            if (col >= N) continue;
            float b0 = 0.f, b1 = 0.f;
            if (EPI != 2 && bias != nullptr) { b0 = bias[col]; b1 = bias[col + 1]; }
            int row = bm + wm + mi * 16 + r0;
            #pragma unroll
            for (int hh = 0; hh < 2; hh++) {
                float t0 = acc[mi][ni][2*hh + 0] + b0;
                float t1 = acc[mi][ni][2*hh + 1] + b1;
                size_t off = (size_t)(row + 8*hh) * N + col;
                if (EPI == 1) {
                    t0 = geluf(t0); t1 = geluf(t1);
                    *(__half2*)(Ch + off) = __floats2half2_rn(t0, t1);
                } else if (EPI == 3) {
                    *(__half2*)(Ch + off) = __floats2half2_rn(t0, t1);
                } else {
                    if (EPI == 2) { t0 *= scale; t1 *= scale; }
                    float2 o; o.x = t0; o.y = t1;
                    *(float2*)(Cf + off) = o;
                }
            }
        }
    }
}

// ---------------------------------------------------------------------------
// Fused GEMM + LayerNorm for N=256 (CTA owns full rows). 512 thr, 16 warps
// (4M x 4N), CTA tile 128x256, single-term A. 1 CTA/SM.
//   MODE 0: y = LN(acc) + PE            (p2)
//   MODE 1: y = LN(acc + bias + hres)   (out_proj / ff2)
// Writes hf (fp32) + hh (fp16).
// ---------------------------------------------------------------------------
#define L_OFF_A  0
#define L_OFF_W  10240
#define L_STAGE  30720
#define L_SMEM   (2*L_STAGE)   // 61440

template<int MODE>
__global__ __launch_bounds__(512, 1)
void gemm_ln256(const __half* __restrict__ Ah, const __half* __restrict__ Wh,
                const float* __restrict__ bias, const float* __restrict__ hres,
                const float* __restrict__ lnw, const float* __restrict__ lnb,
                float* __restrict__ hf, __half* __restrict__ hh_,
                int M, int K)
{
    extern __shared__ __align__(128) char smem[];
    const uint32_t sb = smem_u32(smem);
    const int tid  = threadIdx.x;
    const int wid  = tid >> 5;
    const int lane = tid & 31;
    const int bm = blockIdx.y * 128;
    const int wm = (wid & 3) * 32;
    const int wn = (wid >> 2) * 64;

    float acc[2][8][4];
    #pragma unroll
    for (int mi = 0; mi < 2; mi++)
        #pragma unroll
        for (int ni = 0; ni < 8; ni++)
            #pragma unroll
            for (int e = 0; e < 4; e++) acc[mi][ni][e] = 0.f;

    const int r_ = tid >> 2;   // 0..127
    const int sg = tid & 3;
    auto issue = [&](int c) {
        const uint32_t st = sb + (c & 1) * L_STAGE;
        const size_t kb = (size_t)c * 64 + sg * 16;
        cp16(st + L_OFF_A + r_ * ROWB + sg * 16,
             (const char*)Ah + (size_t)(bm + r_) * K * 2 + kb, 16);
        cp16(st + L_OFF_W + r_ * ROWB + sg * 16,
             (const char*)Wh + (size_t)r_ * K * 2 + kb, 16);
        cp16(st + L_OFF_W + (r_ + 128) * ROWB + sg * 16,
             (const char*)Wh + (size_t)(r_ + 128) * K * 2 + kb, 16);
    };

    const uint32_t a_row = wm + (lane & 15);
    const uint32_t a_kof = (lane >> 4) << 3;
    const uint32_t b_row = wn + (lane & 7) + (((lane >> 4) & 1) << 3);
    const uint32_t b_kof = ((lane >> 3) & 1) << 3;

    auto mma_chunk = [&](uint32_t st) {
        #pragma unroll
        for (int ks = 0; ks < 2; ks++) {
            const uint32_t k0 = ks << 4;
            uint32_t ah_[2][4];
            #pragma unroll
            for (int mi = 0; mi < 2; mi++)
                ldsm4(ah_[mi], st + L_OFF_A + (a_row + mi*16) * ROWB + (k0 + a_kof) * 2);
            uint32_t bh_[8][2];
            #pragma unroll
            for (int nj = 0; nj < 4; nj++) {
                uint32_t r[4];
                ldsm4(r, st + L_OFF_W + (b_row + nj*16) * ROWB + (k0 + b_kof) * 2);
                bh_[2*nj][0] = r[0]; bh_[2*nj][1] = r[1];
                bh_[2*nj+1][0] = r[2]; bh_[2*nj+1][1] = r[3];
            }
            #pragma unroll
            for (int mi = 0; mi < 2; mi++)
                #pragma unroll
                for (int ni = 0; ni < 8; ni++)
                    mma16816h(acc[mi][ni], ah_[mi], bh_[ni]);
        }
    };

    const int nch = K >> 5;
    issue(0); CP_COMMIT();
    for (int c = 0; c < nch; c++) {
        if (c + 1 < nch) { issue(c + 1); CP_COMMIT(); CP_WAIT1(); }
        else             { CP_WAIT0(); }
        __syncthreads();
        mma_chunk(sb + (c & 1) * L_STAGE);
        __syncthreads();
    }

    // ---- epilogue: v = acc (+bias +resid); row-LN over 256 cols ----
    const int r0 = lane >> 2;
    const int cc0 = (lane & 3) << 1;
    const int wnidx = wid >> 2;
    float* rsum = (float*)smem;          // [128][4]
    float* rss  = rsum + 128 * 4;        // [128][4]

    float psum[2][2], pss[2][2];
    #pragma unroll
    for (int mi = 0; mi < 2; mi++)
        #pragma unroll
        for (int hh = 0; hh < 2; hh++) { psum[mi][hh] = 0.f; pss[mi][hh] = 0.f; }

    #pragma unroll
    for (int ni = 0; ni < 8; ni++) {
        int col = wn + ni * 8 + cc0;
        float b0 = 0.f, b1 = 0.f;
        if (MODE == 1) { b0 = bias[col]; b1 = bias[col + 1]; }
        #pragma unroll
        for (int mi = 0; mi < 2; mi++) {
            #pragma unroll
            for (int hh = 0; hh < 2; hh++) {
                int row = bm + wm + mi * 16 + r0 + 8 * hh;
                float t0 = acc[mi][ni][2*hh + 0] + b0;
                float t1 = acc[mi][ni][2*hh + 1] + b1;
                if (MODE == 1) {
                    float2 rr = *(const float2*)(hres + (size_t)row * 256 + col);
                    t0 += rr.x; t1 += rr.y;
                }
                acc[mi][ni][2*hh + 0] = t0;
                acc[mi][ni][2*hh + 1] = t1;
                psum[mi][hh] += t0 + t1;
                pss[mi][hh]  += t0 * t0 + t1 * t1;
            }
        }
    }
    #pragma unroll
    for (int mi = 0; mi < 2; mi++)
        #pragma unroll
        for (int hh = 0; hh < 2; hh++) {
            #pragma unroll
            for (int o = 1; o <= 2; o <<= 1) {
                psum[mi][hh] += __shfl_xor_sync(0xffffffffu, psum[mi][hh], o);
                pss[mi][hh]  += __shfl_xor_sync(0xffffffffu, pss[mi][hh], o);
            }
        }
    if ((lane & 3) == 0) {
        #pragma unroll
        for (int mi = 0; mi < 2; mi++)
            #pragma unroll
            for (int hh = 0; hh < 2; hh++) {
                int rl = wm + mi * 16 + r0 + 8 * hh;
                rsum[rl * 4 + wnidx] = psum[mi][hh];
                rss [rl * 4 + wnidx] = pss[mi][hh];
            }
    }
    __syncthreads();

    float mean[2][2], rstd[2][2];
    #pragma unroll
    for (int mi = 0; mi < 2; mi++)
        #pragma unroll
        for (int hh = 0; hh < 2; hh++) {
            int rl = wm + mi * 16 + r0 + 8 * hh;
            float s = rsum[rl*4+0] + rsum[rl*4+1] + rsum[rl*4+2] + rsum[rl*4+3];
            float q = rss [rl*4+0] + rss [rl*4+1] + rss [rl*4+2] + rss [rl*4+3];
            float m = s * (1.f / 256.f);
            float v = q * (1.f / 256.f) - m * m;
            mean[mi][hh] = m;
            rstd[mi][hh] = rsqrtf(v + 1e-6f);
        }

    #pragma unroll
    for (int ni = 0; ni < 8; ni++) {
        int col = wn + ni * 8 + cc0;
        float w0 = lnw[col], w1 = lnw[col + 1];
        float g0 = lnb[col], g1 = lnb[col + 1];
        #pragma unroll
        for (int mi = 0; mi < 2; mi++) {
            #pragma unroll
            for (int hh = 0; hh < 2; hh++) {
                int row = bm + wm + mi * 16 + r0 + 8 * hh;
                float y0 = (acc[mi][ni][2*hh+0] - mean[mi][hh]) * rstd[mi][hh] * w0 + g0;
                float y1 = (acc[mi][ni][2*hh+1] - mean[mi][hh]) * rstd[mi][hh] * w1 + g1;
                if (MODE == 0) {
                    int t = row % SEQT;
                    float ang = (float)t * expf((float)col * (-9.210340371976184f / 256.f));
                    y0 += sinf(ang);
                    y1 += cosf(ang);
                }
                size_t off = (size_t)row * 256 + col;
                float2 o; o.x = y0; o.y = y1;
                *(float2*)(hf + off) = o;
                *(__half2*)(hh_ + off) = __floats2half2_rn(y0, y1);
            }
        }
    }
}

// ---------------------------------------------------------------------------
// Small kernels
// ---------------------------------------------------------------------------
__global__ void conv_f16(const float* __restrict__ src, __half* __restrict__ dst, long n4)
{
    long i = (long)blockIdx.x * blockDim.x + threadIdx.x;
    if (i >= n4) return;
    float4 v = ((const float4*)src)[i];
    __half2 a = __floats2half2_rn(v.x, v.y);
    __half2 b = __floats2half2_rn(v.z, v.w);
    uint2 u; u.x = *(uint32_t*)&a; u.y = *(uint32_t*)&b;
    ((uint2*)dst)[i] = u;
}

// LN + GELU over rows of 1024 fp16 input -> fp16 output
__global__ void ln_gelu_1024(const __half* __restrict__ buf,
                             __half* __restrict__ dh,
                             const float* __restrict__ w, const float* __restrict__ b)
{
    int row = blockIdx.x;
    const uint2* p = (const uint2*)(buf + (size_t)row * 1024);
    int tid = threadIdx.x;
    uint2 raw = p[tid];
    __half2 x01 = *(__half2*)&raw.x;
    __half2 x23 = *(__half2*)&raw.y;
    float2 f01 = __half22float2(x01);
    float2 f23 = __half22float2(x23);
    float4 x; x.x = f01.x; x.y = f01.y; x.z = f23.x; x.w = f23.y;
    float s  = x.x + x.y + x.z + x.w;
    float ss = x.x*x.x + x.y*x.y + x.z*x.z + x.w*x.w;
    __shared__ float sh[2][8];
    float ws_ = warp_sum(s), wss = warp_sum(ss);
    if ((tid & 31) == 0) { sh[0][tid >> 5] = ws_; sh[1][tid >> 5] = wss; }
    __syncthreads();
    float tot = 0.f, tot2 = 0.f;
    #pragma unroll
    for (int i = 0; i < 8; i++) { tot += sh[0][i]; tot2 += sh[1][i]; }
    float mean = tot * (1.f / 1024.f);
    float var  = tot2 * (1.f / 1024.f) - mean * mean;
    float rstd = rsqrtf(var + 1e-6f);
    float4 wv = ((const float4*)w)[tid];
    float4 bv = ((const float4*)b)[tid];
    float y0 = geluf((x.x - mean) * rstd * wv.x + bv.x);
    float y1 = geluf((x.y - mean) * rstd * wv.y + bv.y);
    float y2 = geluf((x.z - mean) * rstd * wv.z + bv.z);
    float y3 = geluf((x.w - mean) * rstd * wv.w + bv.w);
    __half2 H01 = __floats2half2_rn(y0, y1);
    __half2 H23 = __floats2half2_rn(y2, y3);
    uint2 hu; hu.x = *(uint32_t*)&H01; hu.y = *(uint32_t*)&H23;
    ((uint2*)(dh + (size_t)row * 1024))[tid] = hu;
}

__global__ void norm_rows_256(const float* __restrict__ src,
                              __half* __restrict__ oh, int nrows)
{
    int row  = blockIdx.x * 8 + (threadIdx.x >> 5);
    int lane = threadIdx.x & 31;
    if (row >= nrows) return;
    const float* x = src + (size_t)row * 256;
    float v[8], ss = 0.f;
    #pragma unroll
    for (int i = 0; i < 8; i++) { v[i] = x[lane + 32*i]; ss += v[i]*v[i]; }
    ss = warp_sum(ss);
    float inv = 1.f / fmaxf(sqrtf(ss), 1e-12f);
    size_t base = (size_t)row * 256;
    #pragma unroll
    for (int i = 0; i < 8; i++) {
        int c = lane + 32*i;
        oh[base + c] = __float2half_rn(v[i] * inv);
    }
}

// Attention over fp16 qkv [M, 768], fp16 output [M, 256]
__global__ void attn_kernel(const __half* __restrict__ qkv, __half* __restrict__ oh)
{
    int bh = blockIdx.x;
    int bidx = bh / NHEAD;
    int hh   = bh % NHEAD;
    __shared__ float q[SEQT][HEADD];
    __shared__ float k[SEQT][HEADD];
    __shared__ float v[SEQT][HEADD];
    __shared__ float p[SEQT][SEQT];
    int tid = threadIdx.x;

    for (int idx = tid; idx < SEQT * HEADD; idx += 256) {
        int t = idx / HEADD, d = idx % HEADD;
        size_t off = (size_t)(bidx * SEQT + t) * 768 + hh * HEADD + d;
        q[t][d] = __half2float(qkv[off]);
        k[t][d] = __half2float(qkv[off + 256]);
        v[t][d] = __half2float(qkv[off + 512]);
    }
    __syncthreads();

    for (int idx = tid; idx < SEQT * SEQT; idx += 256) {
        int t = idx / SEQT, s = idx % SEQT;
        if (s <= t) {
            float acc = 0.f;
            #pragma unroll
            for (int d = 0; d < HEADD; d++) acc += q[t][d] * k[s][d];
            p[t][s] = acc * 0.125f;
        } else p[t][s] = 0.f;
    }
    __syncthreads();

    if (tid < SEQT) {
        int t = tid;
        float mx = -1e30f;
        for (int s = 0; s <= t; s++) mx = fmaxf(mx, p[t][s]);
        float sum = 0.f;
        for (int s = 0; s <= t; s++) { float e = expf(p[t][s] - mx); p[t][s] = e; sum += e; }
        float inv = 1.f / sum;
        for (int s = 0; s <= t; s++) p[t][s] *= inv;
        for (int s = t + 1; s < SEQT; s++) p[t][s] = 0.f;
    }
    __syncthreads();

    for (int idx = tid; idx < SEQT * HEADD; idx += 256) {
        int t = idx / HEADD, d = idx % HEADD;
        float acc = 0.f;
        for (int s = 0; s <= t; s++) acc += p[t][s] * v[s][d];
        size_t off = (size_t)(bidx * SEQT + t) * 256 + hh * HEADD + d;
        oh[off] = __float2half_rn(acc);
    }
}

// ---------------------------------------------------------------------------
// Launch
// ---------------------------------------------------------------------------
extern "C" void kernel_launch(void* const* d_in, const int* in_sizes, int n_in,
                              void* d_out, int out_size)
{
    const float* x         = (const float*)d_in[0];
    const float* p1_w      = (const float*)d_in[1];
    const float* p1_b      = (const float*)d_in[2];
    const float* pln1_w    = (const float*)d_in[3];
    const float* pln1_b    = (const float*)d_in[4];
    const float* p2_w      = (const float*)d_in[5];
    const float* pln2_w    = (const float*)d_in[6];
    const float* pln2_b    = (const float*)d_in[7];
    const float* in_proj_w = (const float*)d_in[8];
    const float* in_proj_b = (const float*)d_in[9];
    const float* out_proj_w= (const float*)d_in[10];
    const float* out_proj_b= (const float*)d_in[11];
    const float* ln1_w     = (const float*)d_in[12];
    const float* ln1_b     = (const float*)d_in[13];
    const float* lin1_w    = (const float*)d_in[14];
    const float* lin1_b    = (const float*)d_in[15];
    const float* lin2_w    = (const float*)d_in[16];
    const float* lin2_b    = (const float*)d_in[17];
    const float* ln2_w     = (const float*)d_in[18];
    const float* ln2_b     = (const float*)d_in[19];
    const float* head_w    = (const float*)d_in[20];
    float* out = (float*)d_out;

    float *hf;
    __half *tmp16,*xh,*b1h,*b2h,*hh;
    __half *w1,*w2,*wq,*wo,*wf1,*wf2,*wn;
    cudaGetSymbolAddress((void**)&tmp16, g_tmp);
    cudaGetSymbolAddress((void**)&hf,  g_hf);
    cudaGetSymbolAddress((void**)&xh,  g_xh);
    cudaGetSymbolAddress((void**)&b1h, g_b1h);
    cudaGetSymbolAddress((void**)&b2h, g_b2h);
    cudaGetSymbolAddress((void**)&hh,  g_hh);
    cudaGetSymbolAddress((void**)&w1,  g_w1);  cudaGetSymbolAddress((void**)&w2,  g_w2);
    cudaGetSymbolAddress((void**)&wq,  g_wq);  cudaGetSymbolAddress((void**)&wo,  g_wo);
    cudaGetSymbolAddress((void**)&wf1, g_wf1); cudaGetSymbolAddress((void**)&wf2, g_wf2);
    cudaGetSymbolAddress((void**)&wn,  g_wn);

    cudaFuncSetAttribute(gemm_fp1<1>, cudaFuncAttributeMaxDynamicSharedMemorySize, SMEM_DYN);
    cudaFuncSetAttribute(gemm_fp1<2>, cudaFuncAttributeMaxDynamicSharedMemorySize, SMEM_DYN);
    cudaFuncSetAttribute(gemm_fp1<3>, cudaFuncAttributeMaxDynamicSharedMemorySize, SMEM_DYN);
    cudaFuncSetAttribute(gemm_ln256<0>, cudaFuncAttributeMaxDynamicSharedMemorySize, L_SMEM);
    cudaFuncSetAttribute(gemm_ln256<1>, cudaFuncAttributeMaxDynamicSharedMemorySize, L_SMEM);

    const int M = M_TOK;
    const dim3 blk(256);
    const dim3 blk5(512);
    const int MB = M / 128;  // 320
    #define GRID(N_) dim3(((N_) + 127) / 128, MB)
    #define CONVH(src, dst, n) do { long n4 = (long)(n) / 4; \
        conv_f16<<<(unsigned)((n4 + 255) / 256), 256>>>(src, dst, n4); } while (0)

    // one-time conversions
    CONVH(x, xh, (long)M * 2048);
    CONVH(p1_w,  w1,  1024L * 2048);
    CONVH(p2_w,  w2,  256L * 1024);
    CONVH(in_proj_w, wq, 2L * 768 * 256);
    CONVH(out_proj_w, wo, 2L * 256 * 256);
    CONVH(lin1_w, wf1, 2L * 1024 * 256);
    CONVH(lin2_w, wf2, 2L * 256 * 1024);

    // projector: p1 -> fp16 tmp, LN+GELU (fp16 in/out), fused p2+LN+PE
    gemm_fp1<3><<<GRID(1024), blk, SMEM_DYN>>>(xh, w1, p1_b, nullptr, tmp16,
                                               M, 1024, 2048, 1.f);
    ln_gelu_1024<<<M, blk>>>(tmp16, b1h, pln1_w, pln1_b);
    gemm_ln256<0><<<dim3(1, MB), blk5, L_SMEM>>>(b1h, w2, nullptr, nullptr,
                                                 pln2_w, pln2_b, hf, hh, M, 1024);

    // transformer layers
    for (int i = 0; i < NLAYER; i++) {
        const __half* iq  = wq  + (size_t)i * 768 * 256;
        const __half* io  = wo  + (size_t)i * 256 * 256;
        const __half* if1 = wf1 + (size_t)i * 1024 * 256;
        const __half* if2 = wf2 + (size_t)i * 256 * 1024;
        const float* ipb = in_proj_b + (size_t)i * 768;
        const float* opb = out_proj_b + (size_t)i * 256;
        const float* l1b = lin1_b + (size_t)i * 1024;
        const float* l2b = lin2_b + (size_t)i * 256;

        // qkv -> fp16 tmp, attention reads fp16
        gemm_fp1<3><<<GRID(768), blk, SMEM_DYN>>>(hh, iq, ipb, nullptr, tmp16,
                                                  M, 768, 256, 1.f);
        attn_kernel<<<BATCH * NHEAD, blk>>>(tmp16, b2h);
        gemm_ln256<1><<<dim3(1, MB), blk5, L_SMEM>>>(b2h, io, opb, hf,
                                                     ln1_w + (size_t)i * 256,
                                                     ln1_b + (size_t)i * 256,
                                                     hf, hh, M, 256);
        gemm_fp1<1><<<GRID(1024), blk, SMEM_DYN>>>(hh, if1, l1b, nullptr, b1h,
                                                   M, 1024, 256, 1.f);
        gemm_ln256<1><<<dim3(1, MB), blk5, L_SMEM>>>(b1h, if2, l2b, hf,
                                                     ln2_w + (size_t)i * 256,
                                                     ln2_b + (size_t)i * 256,
                                                     hf, hh, M, 1024);
    }

    // cosine head
    norm_rows_256<<<M / 8, blk>>>(hf, b2h, M);
    norm_rows_256<<<(NCLS + 7) / 8, blk>>>(head_w, wn, NCLS);
    gemm_fp1<2><<<GRID(NCLS), blk, SMEM_DYN>>>(b2h, wn, nullptr, out, nullptr,
                                               M, NCLS, 256, 10.f);
}